// round 3
// baseline (speedup 1.0000x reference)
#include <cuda_runtime.h>
#include <math.h>

#define TT   16
#define NN   2048
#define EE   16384
#define ELN  8192
#define TNV  (TT*NN)   /* 32768 */
#define TEV  (TT*EE)   /* 262144 */
#define HID  128
#define DIN  64

// ---------------- scratch (static device allocations only) ----------------
__device__ float g_deg[TNV];
__device__ float g_dinv[TNV];
__device__ int   g_cntA[TNV];
__device__ int   g_offA[TNV+1];
__device__ int   g_curA[TNV];
__device__ int   g_cntB[NN];
__device__ int   g_offB[NN+1];
__device__ int   g_curB[NN];
__device__ int   g_srcA[TEV];
__device__ float g_normA[TEV];
__device__ int   g_srcB[TEV];

__device__ __align__(16) float g_xw1[TNV*HID];
__device__ __align__(16) float g_h1 [TNV*HID];
__device__ __align__(16) float g_xw2[TNV*HID];
__device__ __align__(16) float g_h2 [TNV*HID];
__device__ __align__(16) float g_weff[NN*HID];

__device__ __align__(16) float g_xwg1[(size_t)TNV*512];
__device__ float g_as1[TNV*4];
__device__ float g_ad1[TNV*4];
__device__ __align__(16) float g_z1 [(size_t)TNV*512];
__device__ __align__(16) float g_xwg2[TNV*64];
__device__ float g_as2[TNV];
__device__ float g_ad2[TNV];
__device__ __align__(16) float g_z2 [TNV*64];

// compile-time buffer selector: avoids any cudaGetSymbolAddress on the host
#define BUF_EXT   (-1)
#define BUF_XW1   0
#define BUF_H1    1
#define BUF_XW2   2
#define BUF_H2    3
#define BUF_WEFF  4
#define BUF_XWG1  5
#define BUF_Z1    6
#define BUF_XWG2  7
#define BUF_Z2    8

template<int ID>
__device__ __forceinline__ float* gbuf() {
    if (ID == BUF_XW1)  return g_xw1;
    if (ID == BUF_H1)   return g_h1;
    if (ID == BUF_XW2)  return g_xw2;
    if (ID == BUF_H2)   return g_h2;
    if (ID == BUF_WEFF) return g_weff;
    if (ID == BUF_XWG1) return g_xwg1;
    if (ID == BUF_Z1)   return g_z1;
    if (ID == BUF_XWG2) return g_xwg2;
    if (ID == BUF_Z2)   return g_z2;
    return nullptr;
}

// ---------------- init ----------------
__global__ void k_init() {
    int i = blockIdx.x*blockDim.x + threadIdx.x;
    if (i < TNV) { g_deg[i]=0.f; g_cntA[i]=0; g_curA[i]=0; }
    if (i < NN)  { g_cntB[i]=0; g_curB[i]=0; }
}

// ---------------- degree + CSR histograms (edge_index is INT32) ----------------
__global__ void k_hist(const int* __restrict__ ei, const float* __restrict__ ea) {
    int idx = blockIdx.x*blockDim.x + threadIdx.x;
    if (idx >= TEV) return;
    int t = idx >> 14, e = idx & (EE-1);
    int dst = ei[(t*2+1)*EE + e] & (NN-1);
    float w = ea[idx];
    atomicAdd(&g_deg[t*NN+dst], w);
    atomicAdd(&g_cntA[t*NN+dst], 1);
    atomicAdd(&g_cntB[dst], 1);
}

// single-block exclusive scan (n multiple of 1024)
__device__ void scan_impl(const int* cnt, int* off, int n) {
    __shared__ int part[1024];
    int tid = threadIdx.x;
    int per = n / 1024;
    int base = tid * per;
    int s = 0;
    for (int i = 0; i < per; i++) s += cnt[base+i];
    part[tid] = s; __syncthreads();
    for (int d = 1; d < 1024; d <<= 1) {
        int v = (tid >= d) ? part[tid-d] : 0;
        __syncthreads();
        part[tid] += v;
        __syncthreads();
    }
    int run = (tid == 0) ? 0 : part[tid-1];
    for (int i = 0; i < per; i++) { off[base+i] = run; run += cnt[base+i]; }
    if (tid == 1023) off[n] = run;
}
__global__ void k_scanA() { scan_impl(g_cntA, g_offA, TNV); }
__global__ void k_scanB() { scan_impl(g_cntB, g_offB, NN); }

__global__ void k_dinv() {
    int i = blockIdx.x*blockDim.x + threadIdx.x;
    if (i < TNV) g_dinv[i] = 1.0f / sqrtf(g_deg[i] + 1.0f);  // +1 = self-loop weight
}

__global__ void k_fill(const int* __restrict__ ei, const float* __restrict__ ea) {
    int idx = blockIdx.x*blockDim.x + threadIdx.x;
    if (idx >= TEV) return;
    int t = idx >> 14, e = idx & (EE-1);
    int src = ei[(t*2  )*EE + e] & (NN-1);
    int dst = ei[(t*2+1)*EE + e] & (NN-1);
    float w = ea[idx];
    float nm = g_dinv[t*NN+src] * w * g_dinv[t*NN+dst];
    int bA = t*NN + dst;
    int p = atomicAdd(&g_curA[bA], 1);
    int slot = g_offA[bA] + p;
    g_srcA[slot] = t*NN + src;
    g_normA[slot] = nm;
    int q = atomicAdd(&g_curB[dst], 1);
    g_srcB[g_offB[dst] + q] = src;
}

__global__ void k_weff(const float* __restrict__ fcw) {
    int i = blockIdx.x*blockDim.x + threadIdx.x;
    if (i >= NN*HID) return;
    int r = i >> 7, c = i & 127;
    g_weff[i] = fcw[r*256 + c] + fcw[r*256 + 128 + c];
}

// ---------------- SGEMM: C[M,Nc] = A[M,K] * B[Nc,K]^T (+bias) ----------------
template<int BM, int BN, int BK, int TM, int TN, int AID, int BID, int CID>
__global__ __launch_bounds__((BM/TM)*(BN/TN))
void sgemm_nt(const float* __restrict__ Aext, const float* __restrict__ Bext,
              const float* __restrict__ bias, float* __restrict__ Cext,
              int M, int Nc, int K) {
    const float* A = (AID < 0) ? Aext : gbuf<AID>();
    const float* B = (BID < 0) ? Bext : gbuf<BID>();
    float*       C = (CID < 0) ? Cext : gbuf<CID>();
    __shared__ float As[BK][BM];
    __shared__ float Bs[BK][BN];
    constexpr int THREADS = (BM/TM)*(BN/TN);
    const int tid = threadIdx.x;
    const int bm = blockIdx.y * BM;
    const int bn = blockIdx.x * BN;
    const int row0 = (tid / (BN/TN)) * TM;
    const int col0 = (tid % (BN/TN)) * TN;
    float acc[TM][TN];
    #pragma unroll
    for (int i = 0; i < TM; i++)
        #pragma unroll
        for (int j = 0; j < TN; j++) acc[i][j] = 0.f;

    for (int k0 = 0; k0 < K; k0 += BK) {
        for (int i = tid; i < BM*BK; i += THREADS) {
            int r = i / BK, c = i % BK;
            As[c][r] = A[(size_t)(bm+r)*K + k0 + c];
        }
        for (int i = tid; i < BN*BK; i += THREADS) {
            int r = i / BK, c = i % BK;
            Bs[c][r] = B[(size_t)(bn+r)*K + k0 + c];
        }
        __syncthreads();
        #pragma unroll
        for (int kk = 0; kk < BK; kk++) {
            float ar[TM], br[TN];
            #pragma unroll
            for (int i = 0; i < TM; i++) ar[i] = As[kk][row0+i];
            #pragma unroll
            for (int j = 0; j < TN; j++) br[j] = Bs[kk][col0+j];
            #pragma unroll
            for (int i = 0; i < TM; i++)
                #pragma unroll
                for (int j = 0; j < TN; j++) acc[i][j] += ar[i]*br[j];
        }
        __syncthreads();
    }
    #pragma unroll
    for (int j = 0; j < TN; j++) {
        float bb = bias ? bias[bn+col0+j] : 0.f;
        #pragma unroll
        for (int i = 0; i < TM; i++) {
            C[(size_t)(bm+row0+i)*Nc + bn+col0+j] = acc[i][j] + bb;
        }
    }
}

// ---------------- GCN aggregation: warp per (t,dst) bucket ----------------
template<int XWID, int OUTID>
__global__ void k_gcn_gather(const float* __restrict__ bias) {
    const float* xw = gbuf<XWID>();
    float* out = gbuf<OUTID>();
    int b = (blockIdx.x*blockDim.x + threadIdx.x) >> 5;
    if (b >= TNV) return;
    int lane = threadIdx.x & 31;
    const float4* xw4 = (const float4*)xw;
    float dv = g_dinv[b];
    float sn = dv*dv;
    float4 sv = xw4[(size_t)b*32 + lane];
    float4 acc = make_float4(sn*sv.x, sn*sv.y, sn*sv.z, sn*sv.w);
    int beg = g_offA[b], end = g_offA[b+1];
    for (int k = beg; k < end; k++) {
        int sr = g_srcA[k];
        float nm = g_normA[k];
        float4 v = xw4[(size_t)sr*32 + lane];
        acc.x += nm*v.x; acc.y += nm*v.y; acc.z += nm*v.z; acc.w += nm*v.w;
    }
    float4 bb = ((const float4*)bias)[lane];
    float4 r;
    r.x = fmaxf(acc.x+bb.x, 0.f); r.y = fmaxf(acc.y+bb.y, 0.f);
    r.z = fmaxf(acc.z+bb.z, 0.f); r.w = fmaxf(acc.w+bb.w, 0.f);
    ((float4*)out)[(size_t)b*32 + lane] = r;
}

// ---------------- attention score dots ----------------
__global__ void k_att1(const float* __restrict__ asrc, const float* __restrict__ adst) {
    const float* xw = g_xwg1;
    int w = (blockIdx.x*blockDim.x + threadIdx.x) >> 5;
    if (w >= TNV*4) return;
    int lane = threadIdx.x & 31;
    int i = w >> 2, h = w & 3;
    const float* row = xw + (size_t)i*512 + h*128;
    const float* s = asrc + h*128;
    const float* d = adst + h*128;
    float accs = 0.f, accd = 0.f;
    for (int j = lane; j < 128; j += 32) {
        float v = row[j];
        accs += v*s[j]; accd += v*d[j];
    }
    for (int o = 16; o; o >>= 1) {
        accs += __shfl_down_sync(0xffffffffu, accs, o);
        accd += __shfl_down_sync(0xffffffffu, accd, o);
    }
    if (!lane) { g_as1[w] = accs; g_ad1[w] = accd; }
}

__global__ void k_att2(const float* __restrict__ asrc, const float* __restrict__ adst) {
    const float* xw = g_xwg2;
    int w = (blockIdx.x*blockDim.x + threadIdx.x) >> 5;
    if (w >= TNV) return;
    int lane = threadIdx.x & 31;
    const float* row = xw + (size_t)w*64;
    float accs = row[lane]*asrc[lane] + row[lane+32]*asrc[lane+32];
    float accd = row[lane]*adst[lane] + row[lane+32]*adst[lane+32];
    for (int o = 16; o; o >>= 1) {
        accs += __shfl_down_sync(0xffffffffu, accs, o);
        accd += __shfl_down_sync(0xffffffffu, accd, o);
    }
    if (!lane) { g_as2[w] = accs; g_ad2[w] = accd; }
}

__device__ __forceinline__ float lrelu(float x) { return x > 0.f ? x : 0.2f*x; }

// ---------------- GAT layer-1 aggregation (dst < NN), 512 threads ----------------
__global__ __launch_bounds__(512)
void k_gat1_gather(const float* __restrict__ bias) {
    const float* xw = g_xwg1;
    float* z = g_z1;
    __shared__ float red[512];
    __shared__ float p_sh[128*4];
    __shared__ int   src_sh[128];
    __shared__ float sden[4];
    int d = blockIdx.x;
    int tid = threadIdx.x;
    int h = tid >> 7, c = tid & 127;
    int beg = g_offB[d], end = g_offB[d+1];
    int nE = end - beg;
    float adh = g_ad1[d*4+h];
    float eself = lrelu(g_as1[d*4+h] + adh);
    float lmax = eself;
    for (int k = c; k < nE; k += 128) {
        int s = g_srcB[beg+k];
        lmax = fmaxf(lmax, lrelu(g_as1[s*4+h] + adh));
    }
    red[tid] = lmax; __syncthreads();
    for (int s = 64; s > 0; s >>= 1) {
        if (c < s) red[tid] = fmaxf(red[tid], red[tid+s]);
        __syncthreads();
    }
    float emax = red[h << 7];
    float pself = expf(eself - emax);
    float acc = pself * xw[(size_t)d*512 + tid];
    float ldenom = (c == 0) ? pself : 0.f;
    for (int base = 0; base < nE; base += 128) {
        int kmax = min(128, nE - base);
        __syncthreads();
        if (tid < kmax) src_sh[tid] = g_srcB[beg + base + tid];
        __syncthreads();
        if (c < kmax) {
            int s = src_sh[c];
            p_sh[c*4 + h] = expf(lrelu(g_as1[s*4+h] + adh) - emax);
        }
        __syncthreads();
        for (int kk = 0; kk < kmax; kk++) {
            float p = p_sh[kk*4 + h];
            acc += p * xw[(size_t)src_sh[kk]*512 + tid];
            if (c == 0) ldenom += p;
        }
    }
    if (c == 0) sden[h] = ldenom;
    __syncthreads();
    float o = acc / (sden[h] + 1e-16f) + bias[tid];
    z[(size_t)d*512 + tid] = fmaxf(o, 0.f);
}

// ---------------- GAT layer-2 aggregation (dst < NN), 64 threads ----------------
__global__ __launch_bounds__(64)
void k_gat2_gather(const float* __restrict__ bias) {
    const float* xw = g_xwg2;
    float* z = g_z2;
    __shared__ float red[64];
    __shared__ float p_sh[64];
    __shared__ int   src_sh[64];
    __shared__ float sden;
    int d = blockIdx.x;
    int tid = threadIdx.x;
    int beg = g_offB[d], end = g_offB[d+1];
    int nE = end - beg;
    float adh = g_ad2[d];
    float eself = lrelu(g_as2[d] + adh);
    float lmax = eself;
    for (int k = tid; k < nE; k += 64)
        lmax = fmaxf(lmax, lrelu(g_as2[g_srcB[beg+k]] + adh));
    red[tid] = lmax; __syncthreads();
    for (int s = 32; s > 0; s >>= 1) {
        if (tid < s) red[tid] = fmaxf(red[tid], red[tid+s]);
        __syncthreads();
    }
    float emax = red[0];
    float pself = expf(eself - emax);
    float acc = pself * xw[d*64 + tid];
    float ldenom = (tid == 0) ? pself : 0.f;
    for (int base = 0; base < nE; base += 64) {
        int kmax = min(64, nE - base);
        __syncthreads();
        if (tid < kmax) {
            int s = g_srcB[beg + base + tid];
            src_sh[tid] = s;
            p_sh[tid] = expf(lrelu(g_as2[s] + adh) - emax);
        }
        __syncthreads();
        for (int kk = 0; kk < kmax; kk++) {
            float p = p_sh[kk];
            acc += p * xw[src_sh[kk]*64 + tid];
            if (tid == 0) ldenom += p;
        }
    }
    if (tid == 0) sden = ldenom;
    __syncthreads();
    z[d*64 + tid] = acc / (sden + 1e-16f) + bias[tid];
}

// ---------------- self-loop-only nodes (row >= NN) ----------------
__global__ void k_zrest1(const float* __restrict__ bias) {
    int i = blockIdx.x*blockDim.x + threadIdx.x;
    if (i >= (TNV-NN)*512) return;
    size_t off = (size_t)NN*512 + i;
    g_z1[off] = fmaxf(g_xwg1[off] + bias[i & 511], 0.f);
}
__global__ void k_zrest2(const float* __restrict__ bias) {
    int i = blockIdx.x*blockDim.x + threadIdx.x;
    if (i >= (TNV-NN)*64) return;
    int off = NN*64 + i;
    g_z2[off] = g_xwg2[off] + bias[i & 63];
}

// ---------------- link prediction (edge_label_index is INT32) ----------------
__global__ void k_link(const int* __restrict__ eli, float* __restrict__ out) {
    const float* z = g_z2;
    int w = (blockIdx.x*blockDim.x + threadIdx.x) >> 5;
    if (w >= ELN) return;
    int lane = threadIdx.x & 31;
    int u = eli[w] & (TNV-1);
    int v = eli[ELN + w] & (TNV-1);
    float s = z[u*64+lane]*z[v*64+lane] + z[u*64+lane+32]*z[v*64+lane+32];
    for (int o = 16; o; o >>= 1) s += __shfl_down_sync(0xffffffffu, s, o);
    if (!lane) out[w] = s;
}

// ---------------- launch ----------------
extern "C" void kernel_launch(void* const* d_in, const int* in_sizes, int n_in,
                              void* d_out, int out_size) {
    const float* x    = (const float*)d_in[0];
    const int*   ei   = (const int*)d_in[1];
    const float* ea   = (const float*)d_in[2];
    const int*   eli  = (const int*)d_in[3];
    const float* c1w = (const float*)d_in[4];
    const float* c1b = (const float*)d_in[5];
    const float* c2w = (const float*)d_in[6];
    const float* c2b = (const float*)d_in[7];
    const float* g1w = (const float*)d_in[8];
    const float* g1as = (const float*)d_in[9];
    const float* g1ad = (const float*)d_in[10];
    const float* g1b = (const float*)d_in[11];
    const float* g2w = (const float*)d_in[12];
    const float* g2as = (const float*)d_in[13];
    const float* g2ad = (const float*)d_in[14];
    const float* g2b = (const float*)d_in[15];
    const float* fcw = (const float*)d_in[16];
    const float* fcb = (const float*)d_in[17];

    float* out  = (float*)d_out;
    float* link = out;
    float* hop  = out + ELN;

    // graph setup
    k_init<<<TNV/256, 256>>>();
    k_hist<<<TEV/256, 256>>>(ei, ea);
    k_scanA<<<1, 1024>>>();
    k_scanB<<<1, 1024>>>();
    k_dinv<<<TNV/256, 256>>>();
    k_fill<<<TEV/256, 256>>>(ei, ea);
    k_weff<<<(NN*HID)/256, 256>>>(fcw);

    // --- GCN hop branch ---
    sgemm_nt<128,128,16,8,8, BUF_EXT,BUF_EXT,BUF_XW1><<<dim3(1,TNV/128), 256>>>(x, c1w, nullptr, nullptr, TNV, 128, 64);
    k_gcn_gather<BUF_XW1,BUF_H1><<<TNV/4, 128>>>(c1b);
    sgemm_nt<128,128,16,8,8, BUF_H1,BUF_EXT,BUF_XW2><<<dim3(1,TNV/128), 256>>>(nullptr, c2w, nullptr, nullptr, TNV, 128, 128);
    k_gcn_gather<BUF_XW2,BUF_H2><<<TNV/4, 128>>>(c2b);
    sgemm_nt<128,128,16,8,8, BUF_H2,BUF_WEFF,BUF_EXT><<<dim3(NN/128,TNV/128), 256>>>(nullptr, nullptr, fcb, hop, TNV, NN, 128);

    // --- GAT link branch ---
    sgemm_nt<128,128,16,8,8, BUF_EXT,BUF_EXT,BUF_XWG1><<<dim3(512/128,TNV/128), 256>>>(x, g1w, nullptr, nullptr, TNV, 512, 64);
    k_att1<<<TNV, 128>>>(g1as, g1ad);
    k_gat1_gather<<<NN, 512>>>(g1b);
    k_zrest1<<<((TNV-NN)*512)/256, 256>>>(g1b);
    sgemm_nt<128,64,16,8,4, BUF_Z1,BUF_EXT,BUF_XWG2><<<dim3(1,TNV/128), 256>>>(nullptr, g2w, nullptr, nullptr, TNV, 64, 512);
    k_att2<<<TNV/4, 128>>>(g2as, g2ad);
    k_gat2_gather<<<NN, 64>>>(g2b);
    k_zrest2<<<((TNV-NN)*64)/256, 256>>>(g2b);
    k_link<<<ELN/4, 128>>>(eli, link);
}

// round 4
// speedup vs baseline: 1.7824x; 1.7824x over previous
#include <cuda_runtime.h>
#include <math.h>
#include <stdint.h>

#define TT   16
#define NN   2048
#define EE   16384
#define ELN  8192
#define TNV  (TT*NN)   /* 32768 */
#define TEV  (TT*EE)   /* 262144 */
#define HID  128
#define DIN  64

// ---------------- scratch (static device allocations only) ----------------
__device__ float g_deg[TNV];
__device__ float g_dinv[TNV];
__device__ int   g_cntA[TNV];
__device__ int   g_offA[TNV+1];
__device__ int   g_curA[TNV];
__device__ int   g_cntB[NN];
__device__ int   g_offB[NN+1];
__device__ int   g_curB[NN];
__device__ int   g_srcA[TEV];
__device__ float g_normA[TEV];
__device__ int   g_srcB[TEV];

__device__ __align__(16) float g_xw1[TNV*HID];
__device__ __align__(16) float g_h1 [TNV*HID];
__device__ __align__(16) float g_xw2[TNV*HID];
__device__ __align__(16) float g_h2 [TNV*HID];
__device__ __align__(16) float g_weff[NN*HID];

__device__ __align__(16) float g_xwg1[(size_t)TNV*512];
__device__ float g_as1[TNV*4];
__device__ float g_ad1[TNV*4];
__device__ __align__(16) float g_z1 [(size_t)TNV*512];
__device__ __align__(16) float g_xwg2[TNV*64];
__device__ float g_as2[TNV];
__device__ float g_ad2[TNV];
__device__ __align__(16) float g_z2 [TNV*64];

#define BUF_EXT   (-1)
#define BUF_XW1   0
#define BUF_H1    1
#define BUF_XW2   2
#define BUF_H2    3
#define BUF_WEFF  4
#define BUF_XWG1  5
#define BUF_Z1    6
#define BUF_XWG2  7
#define BUF_Z2    8

template<int ID>
__device__ __forceinline__ float* gbuf() {
    if (ID == BUF_XW1)  return g_xw1;
    if (ID == BUF_H1)   return g_h1;
    if (ID == BUF_XW2)  return g_xw2;
    if (ID == BUF_H2)   return g_h2;
    if (ID == BUF_WEFF) return g_weff;
    if (ID == BUF_XWG1) return g_xwg1;
    if (ID == BUF_Z1)   return g_z1;
    if (ID == BUF_XWG2) return g_xwg2;
    if (ID == BUF_Z2)   return g_z2;
    return nullptr;
}

// ---------------- init ----------------
__global__ void k_init() {
    int i = blockIdx.x*blockDim.x + threadIdx.x;
    if (i < TNV) { g_deg[i]=0.f; g_cntA[i]=0; g_curA[i]=0; }
    if (i < NN)  { g_cntB[i]=0; g_curB[i]=0; }
}

// ---------------- degree + CSR histograms (edge_index is INT32) ----------------
__global__ void k_hist(const int* __restrict__ ei, const float* __restrict__ ea) {
    int idx = blockIdx.x*blockDim.x + threadIdx.x;
    if (idx >= TEV) return;
    int t = idx >> 14, e = idx & (EE-1);
    int dst = ei[(t*2+1)*EE + e] & (NN-1);
    float w = ea[idx];
    atomicAdd(&g_deg[t*NN+dst], w);
    atomicAdd(&g_cntA[t*NN+dst], 1);
    atomicAdd(&g_cntB[dst], 1);
}

// single-block exclusive scan (n multiple of 1024)
__device__ void scan_impl(const int* cnt, int* off, int n) {
    __shared__ int part[1024];
    int tid = threadIdx.x;
    int per = n / 1024;
    int base = tid * per;
    int s = 0;
    for (int i = 0; i < per; i++) s += cnt[base+i];
    part[tid] = s; __syncthreads();
    for (int d = 1; d < 1024; d <<= 1) {
        int v = (tid >= d) ? part[tid-d] : 0;
        __syncthreads();
        part[tid] += v;
        __syncthreads();
    }
    int run = (tid == 0) ? 0 : part[tid-1];
    for (int i = 0; i < per; i++) { off[base+i] = run; run += cnt[base+i]; }
    if (tid == 1023) off[n] = run;
}
__global__ void k_scanA() { scan_impl(g_cntA, g_offA, TNV); }
__global__ void k_scanB() { scan_impl(g_cntB, g_offB, NN); }

__global__ void k_dinv() {
    int i = blockIdx.x*blockDim.x + threadIdx.x;
    if (i < TNV) g_dinv[i] = 1.0f / sqrtf(g_deg[i] + 1.0f);
}

__global__ void k_fill(const int* __restrict__ ei, const float* __restrict__ ea) {
    int idx = blockIdx.x*blockDim.x + threadIdx.x;
    if (idx >= TEV) return;
    int t = idx >> 14, e = idx & (EE-1);
    int src = ei[(t*2  )*EE + e] & (NN-1);
    int dst = ei[(t*2+1)*EE + e] & (NN-1);
    float w = ea[idx];
    float nm = g_dinv[t*NN+src] * w * g_dinv[t*NN+dst];
    int bA = t*NN + dst;
    int p = atomicAdd(&g_curA[bA], 1);
    int slot = g_offA[bA] + p;
    g_srcA[slot] = t*NN + src;
    g_normA[slot] = nm;
    int q = atomicAdd(&g_curB[dst], 1);
    g_srcB[g_offB[dst] + q] = src;
}

__global__ void k_weff(const float* __restrict__ fcw) {
    int i = blockIdx.x*blockDim.x + threadIdx.x;
    if (i >= NN*HID) return;
    int r = i >> 7, c = i & 127;
    g_weff[i] = fcw[r*256 + c] + fcw[r*256 + 128 + c];
}

// ================= tf32 MMA GEMM: C[M,Nc] = A[M,K]*B[Nc,K]^T (+bias) =============
__device__ __forceinline__ uint32_t f2tf32(float x) {
    uint32_t r; asm("cvt.rna.tf32.f32 %0, %1;" : "=r"(r) : "f"(x)); return r;
}
__device__ __forceinline__ void mma8(float* c, const uint32_t* a, const uint32_t* b) {
    asm volatile("mma.sync.aligned.m16n8k8.row.col.f32.tf32.tf32.f32 "
                 "{%0,%1,%2,%3}, {%4,%5,%6,%7}, {%8,%9}, {%0,%1,%2,%3};"
                 : "+f"(c[0]), "+f"(c[1]), "+f"(c[2]), "+f"(c[3])
                 : "r"(a[0]), "r"(a[1]), "r"(a[2]), "r"(a[3]), "r"(b[0]), "r"(b[1]));
}

template<int BN, int AID, int BID, int CID>
__global__ __launch_bounds__(256)
void mma_nt(const float* __restrict__ Aext, const float* __restrict__ Bext,
            const float* __restrict__ bias, float* __restrict__ Cext,
            int M, int Nc, int K) {
    constexpr int BM = 128, BK = 32;
    constexpr int WROWS = 4, WCOLS = 2;
    constexpr int WM = BM / WROWS;       // 32
    constexpr int WN = BN / WCOLS;       // 64 or 32
    constexpr int MT = WM / 16;          // 2
    constexpr int NT = WN / 8;           // 8 or 4
    __shared__ float As[BM][BK+4];
    __shared__ float Bs[BN][BK+4];
    const float* A = (AID < 0) ? Aext : gbuf<AID>();
    const float* B = (BID < 0) ? Bext : gbuf<BID>();
    float*       C = (CID < 0) ? Cext : gbuf<CID>();

    const int tid = threadIdx.x;
    const int wid = tid >> 5, lane = tid & 31;
    const int wr = wid & (WROWS-1), wc = wid / WROWS;
    const int m0 = wr * WM, n0 = wc * WN;
    const int bm = blockIdx.y * BM, bn = blockIdx.x * BN;
    const int lr = lane >> 2, lc = lane & 3;

    float acc[MT][NT][4];
    #pragma unroll
    for (int i = 0; i < MT; i++)
        #pragma unroll
        for (int j = 0; j < NT; j++)
            #pragma unroll
            for (int q = 0; q < 4; q++) acc[i][j][q] = 0.f;

    for (int k0 = 0; k0 < K; k0 += BK) {
        #pragma unroll
        for (int i = tid; i < BM*8; i += 256) {
            int r = i >> 3, q = i & 7;
            float4 v = *(const float4*)&A[(size_t)(bm+r)*K + k0 + q*4];
            As[r][q*4+0] = v.x; As[r][q*4+1] = v.y; As[r][q*4+2] = v.z; As[r][q*4+3] = v.w;
        }
        #pragma unroll
        for (int i = tid; i < BN*8; i += 256) {
            int r = i >> 3, q = i & 7;
            float4 v = *(const float4*)&B[(size_t)(bn+r)*K + k0 + q*4];
            Bs[r][q*4+0] = v.x; Bs[r][q*4+1] = v.y; Bs[r][q*4+2] = v.z; Bs[r][q*4+3] = v.w;
        }
        __syncthreads();
        #pragma unroll
        for (int kc = 0; kc < BK; kc += 8) {
            uint32_t ah[MT][4], al[MT][4], bh[NT][2], bl[NT][2];
            #pragma unroll
            for (int i = 0; i < MT; i++) {
                int r = m0 + i*16 + lr;
                float x0 = As[r  ][kc + lc];
                float x1 = As[r+8][kc + lc];
                float x2 = As[r  ][kc + lc + 4];
                float x3 = As[r+8][kc + lc + 4];
                ah[i][0] = f2tf32(x0); al[i][0] = f2tf32(x0 - __uint_as_float(ah[i][0]));
                ah[i][1] = f2tf32(x1); al[i][1] = f2tf32(x1 - __uint_as_float(ah[i][1]));
                ah[i][2] = f2tf32(x2); al[i][2] = f2tf32(x2 - __uint_as_float(ah[i][2]));
                ah[i][3] = f2tf32(x3); al[i][3] = f2tf32(x3 - __uint_as_float(ah[i][3]));
            }
            #pragma unroll
            for (int j = 0; j < NT; j++) {
                int r = n0 + j*8 + lr;
                float y0 = Bs[r][kc + lc];
                float y1 = Bs[r][kc + lc + 4];
                bh[j][0] = f2tf32(y0); bl[j][0] = f2tf32(y0 - __uint_as_float(bh[j][0]));
                bh[j][1] = f2tf32(y1); bl[j][1] = f2tf32(y1 - __uint_as_float(bh[j][1]));
            }
            #pragma unroll
            for (int i = 0; i < MT; i++)
                #pragma unroll
                for (int j = 0; j < NT; j++) {
                    mma8(acc[i][j], al[i], bh[j]);
                    mma8(acc[i][j], ah[i], bl[j]);
                    mma8(acc[i][j], ah[i], bh[j]);
                }
        }
        __syncthreads();
    }
    // epilogue
    #pragma unroll
    for (int i = 0; i < MT; i++) {
        int r = bm + m0 + i*16 + lr;
        #pragma unroll
        for (int j = 0; j < NT; j++) {
            int c = bn + n0 + j*8 + lc*2;
            float b0 = bias ? bias[c]   : 0.f;
            float b1 = bias ? bias[c+1] : 0.f;
            float2 v0 = make_float2(acc[i][j][0] + b0, acc[i][j][1] + b1);
            float2 v1 = make_float2(acc[i][j][2] + b0, acc[i][j][3] + b1);
            *(float2*)&C[(size_t)r*Nc + c]     = v0;
            *(float2*)&C[(size_t)(r+8)*Nc + c] = v1;
        }
    }
}

// ---------------- GCN aggregation: warp per (t,dst) bucket ----------------
template<int XWID, int OUTID>
__global__ void k_gcn_gather(const float* __restrict__ bias) {
    const float* xw = gbuf<XWID>();
    float* out = gbuf<OUTID>();
    int b = (blockIdx.x*blockDim.x + threadIdx.x) >> 5;
    if (b >= TNV) return;
    int lane = threadIdx.x & 31;
    const float4* xw4 = (const float4*)xw;
    float dv = g_dinv[b];
    float sn = dv*dv;
    float4 sv = xw4[(size_t)b*32 + lane];
    float4 acc = make_float4(sn*sv.x, sn*sv.y, sn*sv.z, sn*sv.w);
    int beg = g_offA[b], end = g_offA[b+1];
    for (int k = beg; k < end; k++) {
        int sr = g_srcA[k];
        float nm = g_normA[k];
        float4 v = xw4[(size_t)sr*32 + lane];
        acc.x += nm*v.x; acc.y += nm*v.y; acc.z += nm*v.z; acc.w += nm*v.w;
    }
    float4 bb = ((const float4*)bias)[lane];
    float4 r;
    r.x = fmaxf(acc.x+bb.x, 0.f); r.y = fmaxf(acc.y+bb.y, 0.f);
    r.z = fmaxf(acc.z+bb.z, 0.f); r.w = fmaxf(acc.w+bb.w, 0.f);
    ((float4*)out)[(size_t)b*32 + lane] = r;
}

// ---------------- attention score dots ----------------
__global__ void k_att1(const float* __restrict__ asrc, const float* __restrict__ adst) {
    const float* xw = g_xwg1;
    int w = (blockIdx.x*blockDim.x + threadIdx.x) >> 5;
    if (w >= TNV*4) return;
    int lane = threadIdx.x & 31;
    int i = w >> 2, h = w & 3;
    const float* row = xw + (size_t)i*512 + h*128;
    const float* s = asrc + h*128;
    const float* d = adst + h*128;
    float accs = 0.f, accd = 0.f;
    for (int j = lane; j < 128; j += 32) {
        float v = row[j];
        accs += v*s[j]; accd += v*d[j];
    }
    for (int o = 16; o; o >>= 1) {
        accs += __shfl_down_sync(0xffffffffu, accs, o);
        accd += __shfl_down_sync(0xffffffffu, accd, o);
    }
    if (!lane) { g_as1[w] = accs; g_ad1[w] = accd; }
}

__global__ void k_att2(const float* __restrict__ asrc, const float* __restrict__ adst) {
    const float* xw = g_xwg2;
    int w = (blockIdx.x*blockDim.x + threadIdx.x) >> 5;
    if (w >= TNV) return;
    int lane = threadIdx.x & 31;
    const float* row = xw + (size_t)w*64;
    float accs = row[lane]*asrc[lane] + row[lane+32]*asrc[lane+32];
    float accd = row[lane]*adst[lane] + row[lane+32]*adst[lane+32];
    for (int o = 16; o; o >>= 1) {
        accs += __shfl_down_sync(0xffffffffu, accs, o);
        accd += __shfl_down_sync(0xffffffffu, accd, o);
    }
    if (!lane) { g_as2[w] = accs; g_ad2[w] = accd; }
}

__device__ __forceinline__ float lrelu(float x) { return x > 0.f ? x : 0.2f*x; }

// ---------------- GAT layer-1 aggregation (dst < NN), 512 threads ----------------
__global__ __launch_bounds__(512)
void k_gat1_gather(const float* __restrict__ bias) {
    const float* xw = g_xwg1;
    float* z = g_z1;
    __shared__ float red[512];
    __shared__ float p_sh[128*4];
    __shared__ int   src_sh[128];
    __shared__ float sden[4];
    int d = blockIdx.x;
    int tid = threadIdx.x;
    int h = tid >> 7, c = tid & 127;
    int beg = g_offB[d], end = g_offB[d+1];
    int nE = end - beg;
    float adh = g_ad1[d*4+h];
    float eself = lrelu(g_as1[d*4+h] + adh);
    float lmax = eself;
    for (int k = c; k < nE; k += 128) {
        int s = g_srcB[beg+k];
        lmax = fmaxf(lmax, lrelu(g_as1[s*4+h] + adh));
    }
    red[tid] = lmax; __syncthreads();
    for (int s = 64; s > 0; s >>= 1) {
        if (c < s) red[tid] = fmaxf(red[tid], red[tid+s]);
        __syncthreads();
    }
    float emax = red[h << 7];
    float pself = expf(eself - emax);
    float acc = pself * xw[(size_t)d*512 + tid];
    float ldenom = (c == 0) ? pself : 0.f;
    for (int base = 0; base < nE; base += 128) {
        int kmax = min(128, nE - base);
        __syncthreads();
        if (tid < kmax) src_sh[tid] = g_srcB[beg + base + tid];
        __syncthreads();
        if (c < kmax) {
            int s = src_sh[c];
            p_sh[c*4 + h] = expf(lrelu(g_as1[s*4+h] + adh) - emax);
        }
        __syncthreads();
        for (int kk = 0; kk < kmax; kk++) {
            float p = p_sh[kk*4 + h];
            acc += p * xw[(size_t)src_sh[kk]*512 + tid];
            if (c == 0) ldenom += p;
        }
    }
    if (c == 0) sden[h] = ldenom;
    __syncthreads();
    float o = acc / (sden[h] + 1e-16f) + bias[tid];
    z[(size_t)d*512 + tid] = fmaxf(o, 0.f);
}

// ---------------- GAT layer-2 aggregation (dst < NN), 64 threads ----------------
__global__ __launch_bounds__(64)
void k_gat2_gather(const float* __restrict__ bias) {
    const float* xw = g_xwg2;
    float* z = g_z2;
    __shared__ float red[64];
    __shared__ float p_sh[64];
    __shared__ int   src_sh[64];
    __shared__ float sden;
    int d = blockIdx.x;
    int tid = threadIdx.x;
    int beg = g_offB[d], end = g_offB[d+1];
    int nE = end - beg;
    float adh = g_ad2[d];
    float eself = lrelu(g_as2[d] + adh);
    float lmax = eself;
    for (int k = tid; k < nE; k += 64)
        lmax = fmaxf(lmax, lrelu(g_as2[g_srcB[beg+k]] + adh));
    red[tid] = lmax; __syncthreads();
    for (int s = 32; s > 0; s >>= 1) {
        if (tid < s) red[tid] = fmaxf(red[tid], red[tid+s]);
        __syncthreads();
    }
    float emax = red[0];
    float pself = expf(eself - emax);
    float acc = pself * xw[d*64 + tid];
    float ldenom = (tid == 0) ? pself : 0.f;
    for (int base = 0; base < nE; base += 64) {
        int kmax = min(64, nE - base);
        __syncthreads();
        if (tid < kmax) {
            int s = g_srcB[beg + base + tid];
            src_sh[tid] = s;
            p_sh[tid] = expf(lrelu(g_as2[s] + adh) - emax);
        }
        __syncthreads();
        for (int kk = 0; kk < kmax; kk++) {
            float p = p_sh[kk];
            acc += p * xw[src_sh[kk]*64 + tid];
            if (tid == 0) ldenom += p;
        }
    }
    if (tid == 0) sden = ldenom;
    __syncthreads();
    z[d*64 + tid] = acc / (sden + 1e-16f) + bias[tid];
}

// ---------------- self-loop-only nodes (row >= NN) ----------------
__global__ void k_zrest1(const float* __restrict__ bias) {
    int i = blockIdx.x*blockDim.x + threadIdx.x;
    if (i >= (TNV-NN)*512) return;
    size_t off = (size_t)NN*512 + i;
    g_z1[off] = fmaxf(g_xwg1[off] + bias[i & 511], 0.f);
}
__global__ void k_zrest2(const float* __restrict__ bias) {
    int i = blockIdx.x*blockDim.x + threadIdx.x;
    if (i >= (TNV-NN)*64) return;
    int off = NN*64 + i;
    g_z2[off] = g_xwg2[off] + bias[i & 63];
}

// ---------------- link prediction (edge_label_index is INT32) ----------------
__global__ void k_link(const int* __restrict__ eli, float* __restrict__ out) {
    const float* z = g_z2;
    int w = (blockIdx.x*blockDim.x + threadIdx.x) >> 5;
    if (w >= ELN) return;
    int lane = threadIdx.x & 31;
    int u = eli[w] & (TNV-1);
    int v = eli[ELN + w] & (TNV-1);
    float s = z[u*64+lane]*z[v*64+lane] + z[u*64+lane+32]*z[v*64+lane+32];
    for (int o = 16; o; o >>= 1) s += __shfl_down_sync(0xffffffffu, s, o);
    if (!lane) out[w] = s;
}

// ---------------- launch ----------------
extern "C" void kernel_launch(void* const* d_in, const int* in_sizes, int n_in,
                              void* d_out, int out_size) {
    const float* x    = (const float*)d_in[0];
    const int*   ei   = (const int*)d_in[1];
    const float* ea   = (const float*)d_in[2];
    const int*   eli  = (const int*)d_in[3];
    const float* c1w = (const float*)d_in[4];
    const float* c1b = (const float*)d_in[5];
    const float* c2w = (const float*)d_in[6];
    const float* c2b = (const float*)d_in[7];
    const float* g1w = (const float*)d_in[8];
    const float* g1as = (const float*)d_in[9];
    const float* g1ad = (const float*)d_in[10];
    const float* g1b = (const float*)d_in[11];
    const float* g2w = (const float*)d_in[12];
    const float* g2as = (const float*)d_in[13];
    const float* g2ad = (const float*)d_in[14];
    const float* g2b = (const float*)d_in[15];
    const float* fcw = (const float*)d_in[16];
    const float* fcb = (const float*)d_in[17];

    float* out  = (float*)d_out;
    float* link = out;
    float* hop  = out + ELN;

    // graph setup
    k_init<<<TNV/256, 256>>>();
    k_hist<<<TEV/256, 256>>>(ei, ea);
    k_scanA<<<1, 1024>>>();
    k_scanB<<<1, 1024>>>();
    k_dinv<<<TNV/256, 256>>>();
    k_fill<<<TEV/256, 256>>>(ei, ea);
    k_weff<<<(NN*HID)/256, 256>>>(fcw);

    // --- GCN hop branch (tensor-core tf32-split GEMMs) ---
    mma_nt<128, BUF_EXT,BUF_EXT,BUF_XW1><<<dim3(1,TNV/128), 256>>>(x, c1w, nullptr, nullptr, TNV, 128, 64);
    k_gcn_gather<BUF_XW1,BUF_H1><<<TNV/4, 128>>>(c1b);
    mma_nt<128, BUF_H1,BUF_EXT,BUF_XW2><<<dim3(1,TNV/128), 256>>>(nullptr, c2w, nullptr, nullptr, TNV, 128, 128);
    k_gcn_gather<BUF_XW2,BUF_H2><<<TNV/4, 128>>>(c2b);
    mma_nt<128, BUF_H2,BUF_WEFF,BUF_EXT><<<dim3(NN/128,TNV/128), 256>>>(nullptr, nullptr, fcb, hop, TNV, NN, 128);

    // --- GAT link branch ---
    mma_nt<128, BUF_EXT,BUF_EXT,BUF_XWG1><<<dim3(512/128,TNV/128), 256>>>(x, g1w, nullptr, nullptr, TNV, 512, 64);
    k_att1<<<TNV, 128>>>(g1as, g1ad);
    k_gat1_gather<<<NN, 512>>>(g1b);
    k_zrest1<<<((TNV-NN)*512)/256, 256>>>(g1b);
    mma_nt<64, BUF_Z1,BUF_EXT,BUF_XWG2><<<dim3(1,TNV/128), 256>>>(nullptr, g2w, nullptr, nullptr, TNV, 64, 512);
    k_att2<<<TNV/4, 128>>>(g2as, g2ad);
    k_gat2_gather<<<NN, 64>>>(g2b);
    k_zrest2<<<((TNV-NN)*64)/256, 256>>>(g2b);
    k_link<<<ELN/4, 128>>>(eli, link);
}

// round 5
// speedup vs baseline: 1.7880x; 1.0032x over previous
#include <cuda_runtime.h>
#include <math.h>
#include <stdint.h>

#define TT   16
#define NN   2048
#define EE   16384
#define ELN  8192
#define TNV  (TT*NN)   /* 32768 */
#define TEV  (TT*EE)   /* 262144 */
#define HID  128
#define DIN  64

// ---------------- scratch (static device allocations only) ----------------
__device__ float g_deg[TNV];
__device__ float g_dinv[TNV];
__device__ int   g_cntA[TNV];
__device__ int   g_offA[TNV+1];
__device__ int   g_curA[TNV];
__device__ int   g_cntB[NN];
__device__ int   g_offB[NN+1];
__device__ int   g_curB[NN];
__device__ int   g_srcA[TEV];
__device__ float g_normA[TEV];
__device__ int   g_srcB[TEV];

__device__ __align__(16) float g_xw1[TNV*HID];
__device__ __align__(16) float g_h1 [TNV*HID];
__device__ __align__(16) float g_xw2[TNV*HID];
__device__ __align__(16) float g_h2 [TNV*HID];
__device__ __align__(16) float g_weff[NN*HID];

__device__ __align__(16) float g_xwg1[(size_t)TNV*512];
__device__ float g_as1[TNV*4];
__device__ float g_ad1[TNV*4];
__device__ __align__(16) float g_z1 [(size_t)TNV*512];
__device__ __align__(16) float g_xwg2[TNV*64];
__device__ float g_as2[TNV];
__device__ float g_ad2[TNV];
__device__ __align__(16) float g_z2 [TNV*64];

#define BUF_EXT   (-1)
#define BUF_XW1   0
#define BUF_H1    1
#define BUF_XW2   2
#define BUF_H2    3
#define BUF_WEFF  4
#define BUF_XWG1  5
#define BUF_Z1    6
#define BUF_XWG2  7
#define BUF_Z2    8

template<int ID>
__device__ __forceinline__ float* gbuf() {
    if (ID == BUF_XW1)  return g_xw1;
    if (ID == BUF_H1)   return g_h1;
    if (ID == BUF_XW2)  return g_xw2;
    if (ID == BUF_H2)   return g_h2;
    if (ID == BUF_WEFF) return g_weff;
    if (ID == BUF_XWG1) return g_xwg1;
    if (ID == BUF_Z1)   return g_z1;
    if (ID == BUF_XWG2) return g_xwg2;
    if (ID == BUF_Z2)   return g_z2;
    return nullptr;
}

// ---------------- init ----------------
__global__ void k_init() {
    int i = blockIdx.x*blockDim.x + threadIdx.x;
    if (i < TNV) { g_deg[i]=0.f; g_cntA[i]=0; g_curA[i]=0; }
    if (i < NN)  { g_cntB[i]=0; g_curB[i]=0; }
}

// ---------------- degree + CSR histograms (edge_index is INT32) ----------------
__global__ void k_hist(const int* __restrict__ ei, const float* __restrict__ ea) {
    int idx = blockIdx.x*blockDim.x + threadIdx.x;
    if (idx >= TEV) return;
    int t = idx >> 14, e = idx & (EE-1);
    int dst = ei[(t*2+1)*EE + e] & (NN-1);
    float w = ea[idx];
    atomicAdd(&g_deg[t*NN+dst], w);
    atomicAdd(&g_cntA[t*NN+dst], 1);
    atomicAdd(&g_cntB[dst], 1);
}

// single-block exclusive scan (n multiple of 1024)
__device__ void scan_impl(const int* cnt, int* off, int n) {
    __shared__ int part[1024];
    int tid = threadIdx.x;
    int per = n / 1024;
    int base = tid * per;
    int s = 0;
    for (int i = 0; i < per; i++) s += cnt[base+i];
    part[tid] = s; __syncthreads();
    for (int d = 1; d < 1024; d <<= 1) {
        int v = (tid >= d) ? part[tid-d] : 0;
        __syncthreads();
        part[tid] += v;
        __syncthreads();
    }
    int run = (tid == 0) ? 0 : part[tid-1];
    for (int i = 0; i < per; i++) { off[base+i] = run; run += cnt[base+i]; }
    if (tid == 1023) off[n] = run;
}
__global__ void k_scanA() { scan_impl(g_cntA, g_offA, TNV); }
__global__ void k_scanB() { scan_impl(g_cntB, g_offB, NN); }

__global__ void k_dinv() {
    int i = blockIdx.x*blockDim.x + threadIdx.x;
    if (i < TNV) g_dinv[i] = 1.0f / sqrtf(g_deg[i] + 1.0f);
}

__global__ void k_fill(const int* __restrict__ ei, const float* __restrict__ ea) {
    int idx = blockIdx.x*blockDim.x + threadIdx.x;
    if (idx >= TEV) return;
    int t = idx >> 14, e = idx & (EE-1);
    int src = ei[(t*2  )*EE + e] & (NN-1);
    int dst = ei[(t*2+1)*EE + e] & (NN-1);
    float w = ea[idx];
    float nm = g_dinv[t*NN+src] * w * g_dinv[t*NN+dst];
    int bA = t*NN + dst;
    int p = atomicAdd(&g_curA[bA], 1);
    int slot = g_offA[bA] + p;
    g_srcA[slot] = t*NN + src;
    g_normA[slot] = nm;
    int q = atomicAdd(&g_curB[dst], 1);
    g_srcB[g_offB[dst] + q] = src;
}

__global__ void k_weff(const float* __restrict__ fcw) {
    int i = blockIdx.x*blockDim.x + threadIdx.x;
    if (i >= NN*HID) return;
    int r = i >> 7, c = i & 127;
    g_weff[i] = fcw[r*256 + c] + fcw[r*256 + 128 + c];
}

// ================= tf32 MMA GEMM: C[M,Nc] = A[M,K]*B[Nc,K]^T (+bias) =============
// hi/lo split precomputed in shared memory during the cooperative load:
// mainloop is pure LDS + HMMA (no per-warp conversions).
__device__ __forceinline__ uint32_t f2tf32(float x) {
    uint32_t r; asm("cvt.rna.tf32.f32 %0, %1;" : "=r"(r) : "f"(x)); return r;
}
__device__ __forceinline__ void mma8(float* c, const uint32_t* a, const uint32_t* b) {
    asm volatile("mma.sync.aligned.m16n8k8.row.col.f32.tf32.tf32.f32 "
                 "{%0,%1,%2,%3}, {%4,%5,%6,%7}, {%8,%9}, {%0,%1,%2,%3};"
                 : "+f"(c[0]), "+f"(c[1]), "+f"(c[2]), "+f"(c[3])
                 : "r"(a[0]), "r"(a[1]), "r"(a[2]), "r"(a[3]), "r"(b[0]), "r"(b[1]));
}

template<int BN, int AID, int BID, int CID>
__global__ __launch_bounds__(256)
void mma_nt(const float* __restrict__ Aext, const float* __restrict__ Bext,
            const float* __restrict__ bias, float* __restrict__ Cext,
            int M, int Nc, int K) {
    constexpr int BM = 128, BK = 16, BKP = BK + 4;
    constexpr int WROWS = 4, WCOLS = 2;
    constexpr int WM = BM / WROWS;       // 32
    constexpr int WN = BN / WCOLS;       // 64 or 32
    constexpr int MT = WM / 16;          // 2
    constexpr int NT = WN / 8;           // 8 or 4
    __shared__ uint32_t As_h[BM][BKP];
    __shared__ uint32_t As_l[BM][BKP];
    __shared__ uint32_t Bs_h[BN][BKP];
    __shared__ uint32_t Bs_l[BN][BKP];
    const float* A = (AID < 0) ? Aext : gbuf<AID>();
    const float* B = (BID < 0) ? Bext : gbuf<BID>();
    float*       C = (CID < 0) ? Cext : gbuf<CID>();

    const int tid = threadIdx.x;
    const int wid = tid >> 5, lane = tid & 31;
    const int wr = wid & (WROWS-1), wc = wid / WROWS;
    const int m0 = wr * WM, n0 = wc * WN;
    const int bm = blockIdx.y * BM, bn = blockIdx.x * BN;
    const int lr = lane >> 2, lc = lane & 3;

    float acc[MT][NT][4];
    #pragma unroll
    for (int i = 0; i < MT; i++)
        #pragma unroll
        for (int j = 0; j < NT; j++)
            #pragma unroll
            for (int q = 0; q < 4; q++) acc[i][j][q] = 0.f;

    for (int k0 = 0; k0 < K; k0 += BK) {
        #pragma unroll
        for (int i = tid; i < BM*4; i += 256) {
            int r = i >> 2, q = (i & 3) * 4;
            float4 v = *(const float4*)&A[(size_t)(bm+r)*K + k0 + q];
            uint32_t h0 = f2tf32(v.x), h1 = f2tf32(v.y), h2 = f2tf32(v.z), h3 = f2tf32(v.w);
            As_h[r][q+0] = h0; As_l[r][q+0] = f2tf32(v.x - __uint_as_float(h0));
            As_h[r][q+1] = h1; As_l[r][q+1] = f2tf32(v.y - __uint_as_float(h1));
            As_h[r][q+2] = h2; As_l[r][q+2] = f2tf32(v.z - __uint_as_float(h2));
            As_h[r][q+3] = h3; As_l[r][q+3] = f2tf32(v.w - __uint_as_float(h3));
        }
        #pragma unroll
        for (int i = tid; i < BN*4; i += 256) {
            int r = i >> 2, q = (i & 3) * 4;
            float4 v = *(const float4*)&B[(size_t)(bn+r)*K + k0 + q];
            uint32_t h0 = f2tf32(v.x), h1 = f2tf32(v.y), h2 = f2tf32(v.z), h3 = f2tf32(v.w);
            Bs_h[r][q+0] = h0; Bs_l[r][q+0] = f2tf32(v.x - __uint_as_float(h0));
            Bs_h[r][q+1] = h1; Bs_l[r][q+1] = f2tf32(v.y - __uint_as_float(h1));
            Bs_h[r][q+2] = h2; Bs_l[r][q+2] = f2tf32(v.z - __uint_as_float(h2));
            Bs_h[r][q+3] = h3; Bs_l[r][q+3] = f2tf32(v.w - __uint_as_float(h3));
        }
        __syncthreads();
        #pragma unroll
        for (int kc = 0; kc < BK; kc += 8) {
            uint32_t ah[MT][4], al[MT][4], bh[NT][2], bl[NT][2];
            #pragma unroll
            for (int i = 0; i < MT; i++) {
                int r = m0 + i*16 + lr;
                ah[i][0] = As_h[r  ][kc + lc];     al[i][0] = As_l[r  ][kc + lc];
                ah[i][1] = As_h[r+8][kc + lc];     al[i][1] = As_l[r+8][kc + lc];
                ah[i][2] = As_h[r  ][kc + lc + 4]; al[i][2] = As_l[r  ][kc + lc + 4];
                ah[i][3] = As_h[r+8][kc + lc + 4]; al[i][3] = As_l[r+8][kc + lc + 4];
            }
            #pragma unroll
            for (int j = 0; j < NT; j++) {
                int r = n0 + j*8 + lr;
                bh[j][0] = Bs_h[r][kc + lc];     bl[j][0] = Bs_l[r][kc + lc];
                bh[j][1] = Bs_h[r][kc + lc + 4]; bl[j][1] = Bs_l[r][kc + lc + 4];
            }
            #pragma unroll
            for (int i = 0; i < MT; i++)
                #pragma unroll
                for (int j = 0; j < NT; j++) {
                    mma8(acc[i][j], al[i], bh[j]);
                    mma8(acc[i][j], ah[i], bl[j]);
                    mma8(acc[i][j], ah[i], bh[j]);
                }
        }
        __syncthreads();
    }
    // epilogue
    #pragma unroll
    for (int i = 0; i < MT; i++) {
        int r = bm + m0 + i*16 + lr;
        #pragma unroll
        for (int j = 0; j < NT; j++) {
            int c = bn + n0 + j*8 + lc*2;
            float b0 = bias ? bias[c]   : 0.f;
            float b1 = bias ? bias[c+1] : 0.f;
            float2 v0 = make_float2(acc[i][j][0] + b0, acc[i][j][1] + b1);
            float2 v1 = make_float2(acc[i][j][2] + b0, acc[i][j][3] + b1);
            *(float2*)&C[(size_t)r*Nc + c]     = v0;
            *(float2*)&C[(size_t)(r+8)*Nc + c] = v1;
        }
    }
}

// ---------------- GCN aggregation: warp per (t,dst) bucket ----------------
template<int XWID, int OUTID>
__global__ void k_gcn_gather(const float* __restrict__ bias) {
    const float* xw = gbuf<XWID>();
    float* out = gbuf<OUTID>();
    int b = (blockIdx.x*blockDim.x + threadIdx.x) >> 5;
    if (b >= TNV) return;
    int lane = threadIdx.x & 31;
    const float4* xw4 = (const float4*)xw;
    float dv = g_dinv[b];
    float sn = dv*dv;
    float4 sv = xw4[(size_t)b*32 + lane];
    float4 acc = make_float4(sn*sv.x, sn*sv.y, sn*sv.z, sn*sv.w);
    int beg = g_offA[b], end = g_offA[b+1];
    for (int k = beg; k < end; k++) {
        int sr = g_srcA[k];
        float nm = g_normA[k];
        float4 v = xw4[(size_t)sr*32 + lane];
        acc.x += nm*v.x; acc.y += nm*v.y; acc.z += nm*v.z; acc.w += nm*v.w;
    }
    float4 bb = ((const float4*)bias)[lane];
    float4 r;
    r.x = fmaxf(acc.x+bb.x, 0.f); r.y = fmaxf(acc.y+bb.y, 0.f);
    r.z = fmaxf(acc.z+bb.z, 0.f); r.w = fmaxf(acc.w+bb.w, 0.f);
    ((float4*)out)[(size_t)b*32 + lane] = r;
}

// ---------------- attention score dots ----------------
__global__ void k_att1(const float* __restrict__ asrc, const float* __restrict__ adst) {
    const float* xw = g_xwg1;
    int w = (blockIdx.x*blockDim.x + threadIdx.x) >> 5;
    if (w >= TNV*4) return;
    int lane = threadIdx.x & 31;
    int i = w >> 2, h = w & 3;
    const float* row = xw + (size_t)i*512 + h*128;
    const float* s = asrc + h*128;
    const float* d = adst + h*128;
    float accs = 0.f, accd = 0.f;
    for (int j = lane; j < 128; j += 32) {
        float v = row[j];
        accs += v*s[j]; accd += v*d[j];
    }
    for (int o = 16; o; o >>= 1) {
        accs += __shfl_down_sync(0xffffffffu, accs, o);
        accd += __shfl_down_sync(0xffffffffu, accd, o);
    }
    if (!lane) { g_as1[w] = accs; g_ad1[w] = accd; }
}

__global__ void k_att2(const float* __restrict__ asrc, const float* __restrict__ adst) {
    const float* xw = g_xwg2;
    int w = (blockIdx.x*blockDim.x + threadIdx.x) >> 5;
    if (w >= TNV) return;
    int lane = threadIdx.x & 31;
    const float* row = xw + (size_t)w*64;
    float accs = row[lane]*asrc[lane] + row[lane+32]*asrc[lane+32];
    float accd = row[lane]*adst[lane] + row[lane+32]*adst[lane+32];
    for (int o = 16; o; o >>= 1) {
        accs += __shfl_down_sync(0xffffffffu, accs, o);
        accd += __shfl_down_sync(0xffffffffu, accd, o);
    }
    if (!lane) { g_as2[w] = accs; g_ad2[w] = accd; }
}

__device__ __forceinline__ float lrelu(float x) { return x > 0.f ? x : 0.2f*x; }

// ---------------- GAT layer-1 aggregation (dst < NN), 512 threads ----------------
__global__ __launch_bounds__(512)
void k_gat1_gather(const float* __restrict__ bias) {
    const float* xw = g_xwg1;
    float* z = g_z1;
    __shared__ float red[512];
    __shared__ float p_sh[128*4];
    __shared__ int   src_sh[128];
    __shared__ float sden[4];
    int d = blockIdx.x;
    int tid = threadIdx.x;
    int h = tid >> 7, c = tid & 127;
    int beg = g_offB[d], end = g_offB[d+1];
    int nE = end - beg;
    float adh = g_ad1[d*4+h];
    float eself = lrelu(g_as1[d*4+h] + adh);
    float lmax = eself;
    for (int k = c; k < nE; k += 128) {
        int s = g_srcB[beg+k];
        lmax = fmaxf(lmax, lrelu(g_as1[s*4+h] + adh));
    }
    red[tid] = lmax; __syncthreads();
    for (int s = 64; s > 0; s >>= 1) {
        if (c < s) red[tid] = fmaxf(red[tid], red[tid+s]);
        __syncthreads();
    }
    float emax = red[h << 7];
    float pself = expf(eself - emax);
    float acc = pself * xw[(size_t)d*512 + tid];
    float ldenom = (c == 0) ? pself : 0.f;
    for (int base = 0; base < nE; base += 128) {
        int kmax = min(128, nE - base);
        __syncthreads();
        if (tid < kmax) src_sh[tid] = g_srcB[beg + base + tid];
        __syncthreads();
        if (c < kmax) {
            int s = src_sh[c];
            p_sh[c*4 + h] = expf(lrelu(g_as1[s*4+h] + adh) - emax);
        }
        __syncthreads();
        for (int kk = 0; kk < kmax; kk++) {
            float p = p_sh[kk*4 + h];
            acc += p * xw[(size_t)src_sh[kk]*512 + tid];
            if (c == 0) ldenom += p;
        }
    }
    if (c == 0) sden[h] = ldenom;
    __syncthreads();
    float o = acc / (sden[h] + 1e-16f) + bias[tid];
    z[(size_t)d*512 + tid] = fmaxf(o, 0.f);
}

// ---------------- GAT layer-2 aggregation (dst < NN), 64 threads ----------------
__global__ __launch_bounds__(64)
void k_gat2_gather(const float* __restrict__ bias) {
    const float* xw = g_xwg2;
    float* z = g_z2;
    __shared__ float red[64];
    __shared__ float p_sh[64];
    __shared__ int   src_sh[64];
    __shared__ float sden;
    int d = blockIdx.x;
    int tid = threadIdx.x;
    int beg = g_offB[d], end = g_offB[d+1];
    int nE = end - beg;
    float adh = g_ad2[d];
    float eself = lrelu(g_as2[d] + adh);
    float lmax = eself;
    for (int k = tid; k < nE; k += 64)
        lmax = fmaxf(lmax, lrelu(g_as2[g_srcB[beg+k]] + adh));
    red[tid] = lmax; __syncthreads();
    for (int s = 32; s > 0; s >>= 1) {
        if (tid < s) red[tid] = fmaxf(red[tid], red[tid+s]);
        __syncthreads();
    }
    float emax = red[0];
    float pself = expf(eself - emax);
    float acc = pself * xw[d*64 + tid];
    float ldenom = (tid == 0) ? pself : 0.f;
    for (int base = 0; base < nE; base += 64) {
        int kmax = min(64, nE - base);
        __syncthreads();
        if (tid < kmax) {
            int s = g_srcB[beg + base + tid];
            src_sh[tid] = s;
            p_sh[tid] = expf(lrelu(g_as2[s] + adh) - emax);
        }
        __syncthreads();
        for (int kk = 0; kk < kmax; kk++) {
            float p = p_sh[kk];
            acc += p * xw[src_sh[kk]*64 + tid];
            if (tid == 0) ldenom += p;
        }
    }
    if (tid == 0) sden = ldenom;
    __syncthreads();
    z[d*64 + tid] = acc / (sden + 1e-16f) + bias[tid];
}

// ---------------- self-loop-only nodes (row >= NN) ----------------
__global__ void k_zrest1(const float* __restrict__ bias) {
    int i = blockIdx.x*blockDim.x + threadIdx.x;
    if (i >= (TNV-NN)*512) return;
    size_t off = (size_t)NN*512 + i;
    g_z1[off] = fmaxf(g_xwg1[off] + bias[i & 511], 0.f);
}
__global__ void k_zrest2(const float* __restrict__ bias) {
    int i = blockIdx.x*blockDim.x + threadIdx.x;
    if (i >= (TNV-NN)*64) return;
    int off = NN*64 + i;
    g_z2[off] = g_xwg2[off] + bias[i & 63];
}

// ---------------- link prediction (edge_label_index is INT32) ----------------
__global__ void k_link(const int* __restrict__ eli, float* __restrict__ out) {
    const float* z = g_z2;
    int w = (blockIdx.x*blockDim.x + threadIdx.x) >> 5;
    if (w >= ELN) return;
    int lane = threadIdx.x & 31;
    int u = eli[w] & (TNV-1);
    int v = eli[ELN + w] & (TNV-1);
    float s = z[u*64+lane]*z[v*64+lane] + z[u*64+lane+32]*z[v*64+lane+32];
    for (int o = 16; o; o >>= 1) s += __shfl_down_sync(0xffffffffu, s, o);
    if (!lane) out[w] = s;
}

// ---------------- launch ----------------
extern "C" void kernel_launch(void* const* d_in, const int* in_sizes, int n_in,
                              void* d_out, int out_size) {
    const float* x    = (const float*)d_in[0];
    const int*   ei   = (const int*)d_in[1];
    const float* ea   = (const float*)d_in[2];
    const int*   eli  = (const int*)d_in[3];
    const float* c1w = (const float*)d_in[4];
    const float* c1b = (const float*)d_in[5];
    const float* c2w = (const float*)d_in[6];
    const float* c2b = (const float*)d_in[7];
    const float* g1w = (const float*)d_in[8];
    const float* g1as = (const float*)d_in[9];
    const float* g1ad = (const float*)d_in[10];
    const float* g1b = (const float*)d_in[11];
    const float* g2w = (const float*)d_in[12];
    const float* g2as = (const float*)d_in[13];
    const float* g2ad = (const float*)d_in[14];
    const float* g2b = (const float*)d_in[15];
    const float* fcw = (const float*)d_in[16];
    const float* fcb = (const float*)d_in[17];

    float* out  = (float*)d_out;
    float* link = out;
    float* hop  = out + ELN;

    // setup; GAT1 GEMM placed at stream-launch index 3 so the fixed ncu
    // window (-s 5 -c 1, which has sampled index 3 in both prior rounds)
    // profiles a GEMM instead of k_scanB.
    k_init<<<TNV/256, 256>>>();                                   // 0
    k_hist<<<TEV/256, 256>>>(ei, ea);                             // 1
    k_scanA<<<1, 1024>>>();                                       // 2
    mma_nt<128, BUF_EXT,BUF_EXT,BUF_XWG1><<<dim3(512/128,TNV/128), 256>>>(x, g1w, nullptr, nullptr, TNV, 512, 64);  // 3
    k_scanB<<<1, 1024>>>();                                       // 4
    k_dinv<<<TNV/256, 256>>>();                                   // 5
    k_fill<<<TEV/256, 256>>>(ei, ea);                             // 6
    k_weff<<<(NN*HID)/256, 256>>>(fcw);                           // 7

    // --- GCN hop branch ---
    mma_nt<128, BUF_EXT,BUF_EXT,BUF_XW1><<<dim3(1,TNV/128), 256>>>(x, c1w, nullptr, nullptr, TNV, 128, 64);
    k_gcn_gather<BUF_XW1,BUF_H1><<<TNV/4, 128>>>(c1b);
    mma_nt<128, BUF_H1,BUF_EXT,BUF_XW2><<<dim3(1,TNV/128), 256>>>(nullptr, c2w, nullptr, nullptr, TNV, 128, 128);
    k_gcn_gather<BUF_XW2,BUF_H2><<<TNV/4, 128>>>(c2b);
    mma_nt<128, BUF_H2,BUF_WEFF,BUF_EXT><<<dim3(NN/128,TNV/128), 256>>>(nullptr, nullptr, fcb, hop, TNV, NN, 128);

    // --- GAT link branch (xwg1 GEMM already issued above) ---
    k_att1<<<TNV, 128>>>(g1as, g1ad);
    k_gat1_gather<<<NN, 512>>>(g1b);
    k_zrest1<<<((TNV-NN)*512)/256, 256>>>(g1b);
    mma_nt<64, BUF_Z1,BUF_EXT,BUF_XWG2><<<dim3(1,TNV/128), 256>>>(nullptr, g2w, nullptr, nullptr, TNV, 64, 512);
    k_att2<<<TNV/4, 128>>>(g2as, g2ad);
    k_gat2_gather<<<NN, 64>>>(g2b);
    k_zrest2<<<((TNV-NN)*64)/256, 256>>>(g2b);
    k_link<<<ELN/4, 128>>>(eli, link);
}

// round 6
// speedup vs baseline: 2.3880x; 1.3355x over previous
#include <cuda_runtime.h>
#include <cuda_bf16.h>
#include <math.h>
#include <stdint.h>

#define TT   16
#define NN   2048
#define EE   16384
#define ELN  8192
#define TNV  (TT*NN)   /* 32768 */
#define TEV  (TT*EE)   /* 262144 */
#define HID  128
#define DIN  64

// ---------------- scratch (static device allocations only) ----------------
__device__ float g_deg[TNV];
__device__ float g_dinv[TNV];
__device__ int   g_cntA[TNV];
__device__ int   g_offA[TNV+1];
__device__ int   g_curA[TNV];
__device__ int   g_cntB[NN];
__device__ int   g_offB[NN+1];
__device__ int   g_curB[NN];
__device__ int   g_srcA[TEV];
__device__ float g_normA[TEV];
__device__ int   g_srcB[TEV];

__device__ __align__(16) float g_xw1[TNV*HID];
__device__ __align__(16) float g_h1 [TNV*HID];
__device__ __align__(16) float g_xw2[TNV*HID];
__device__ __align__(16) float g_h2 [TNV*HID];
__device__ __align__(16) float g_weff[NN*HID];

__device__ __align__(16) float g_xwg1[(size_t)TNV*512];
__device__ float g_as1[TNV*4];
__device__ float g_ad1[TNV*4];
__device__ __align__(16) float g_z1 [(size_t)TNV*512];
__device__ __align__(16) float g_xwg2[TNV*64];
__device__ float g_as2[TNV];
__device__ float g_ad2[TNV];
__device__ __align__(16) float g_z2 [TNV*64];

#define BUF_EXT   (-1)
#define BUF_XW1   0
#define BUF_H1    1
#define BUF_XW2   2
#define BUF_H2    3
#define BUF_WEFF  4
#define BUF_XWG1  5
#define BUF_Z1    6
#define BUF_XWG2  7
#define BUF_Z2    8

template<int ID>
__device__ __forceinline__ float* gbuf() {
    if (ID == BUF_XW1)  return g_xw1;
    if (ID == BUF_H1)   return g_h1;
    if (ID == BUF_XW2)  return g_xw2;
    if (ID == BUF_H2)   return g_h2;
    if (ID == BUF_WEFF) return g_weff;
    if (ID == BUF_XWG1) return g_xwg1;
    if (ID == BUF_Z1)   return g_z1;
    if (ID == BUF_XWG2) return g_xwg2;
    if (ID == BUF_Z2)   return g_z2;
    return nullptr;
}

// ---------------- init ----------------
__global__ void k_init() {
    int i = blockIdx.x*blockDim.x + threadIdx.x;
    if (i < TNV) { g_deg[i]=0.f; g_cntA[i]=0; g_curA[i]=0; }
    if (i < NN)  { g_cntB[i]=0; g_curB[i]=0; }
}

// ---------------- degree + CSR histograms (edge_index is INT32) ----------------
__global__ void k_hist(const int* __restrict__ ei, const float* __restrict__ ea) {
    int idx = blockIdx.x*blockDim.x + threadIdx.x;
    if (idx >= TEV) return;
    int t = idx >> 14, e = idx & (EE-1);
    int dst = ei[(t*2+1)*EE + e] & (NN-1);
    float w = ea[idx];
    atomicAdd(&g_deg[t*NN+dst], w);
    atomicAdd(&g_cntA[t*NN+dst], 1);
    atomicAdd(&g_cntB[dst], 1);
}

// single-block exclusive scan (n multiple of 1024)
__device__ void scan_impl(const int* cnt, int* off, int n) {
    __shared__ int part[1024];
    int tid = threadIdx.x;
    int per = n / 1024;
    int base = tid * per;
    int s = 0;
    for (int i = 0; i < per; i++) s += cnt[base+i];
    part[tid] = s; __syncthreads();
    for (int d = 1; d < 1024; d <<= 1) {
        int v = (tid >= d) ? part[tid-d] : 0;
        __syncthreads();
        part[tid] += v;
        __syncthreads();
    }
    int run = (tid == 0) ? 0 : part[tid-1];
    for (int i = 0; i < per; i++) { off[base+i] = run; run += cnt[base+i]; }
    if (tid == 1023) off[n] = run;
}
__global__ void k_scanA() { scan_impl(g_cntA, g_offA, TNV); }
__global__ void k_scanB() { scan_impl(g_cntB, g_offB, NN); }

__global__ void k_dinv() {
    int i = blockIdx.x*blockDim.x + threadIdx.x;
    if (i < TNV) g_dinv[i] = 1.0f / sqrtf(g_deg[i] + 1.0f);
}

__global__ void k_fill(const int* __restrict__ ei, const float* __restrict__ ea) {
    int idx = blockIdx.x*blockDim.x + threadIdx.x;
    if (idx >= TEV) return;
    int t = idx >> 14, e = idx & (EE-1);
    int src = ei[(t*2  )*EE + e] & (NN-1);
    int dst = ei[(t*2+1)*EE + e] & (NN-1);
    float w = ea[idx];
    float nm = g_dinv[t*NN+src] * w * g_dinv[t*NN+dst];
    int bA = t*NN + dst;
    int p = atomicAdd(&g_curA[bA], 1);
    int slot = g_offA[bA] + p;
    g_srcA[slot] = t*NN + src;
    g_normA[slot] = nm;
    int q = atomicAdd(&g_curB[dst], 1);
    g_srcB[g_offB[dst] + q] = src;
}

__global__ void k_weff(const float* __restrict__ fcw) {
    int i = blockIdx.x*blockDim.x + threadIdx.x;
    if (i >= NN*HID) return;
    int r = i >> 7, c = i & 127;
    g_weff[i] = fcw[r*256 + c] + fcw[r*256 + 128 + c];
}

// ============ bf16x3 MMA GEMM: C[M,Nc] = A[M,K]*B[Nc,K]^T (+bias) ============
// fp32 split into bf16 hi+lo at load time; mainloop = LDS + m16n8k16 bf16 MMA.
// D ~= Ah*Bh + Ah*Bl + Al*Bh  (lo*lo term ~2^-16 relative, dropped)
__device__ __forceinline__ uint32_t packbf2(float lo_elem, float hi_elem) {
    // lower 16 bits = element k (lo_elem), upper = element k+1
    uint32_t a = (uint32_t)__bfloat16_as_ushort(__float2bfloat16_rn(lo_elem));
    uint32_t b = (uint32_t)__bfloat16_as_ushort(__float2bfloat16_rn(hi_elem));
    return (b << 16) | a;
}
__device__ __forceinline__ float bf_hi_f(float x) {
    return __bfloat162float(__float2bfloat16_rn(x));
}
__device__ __forceinline__ void mma16(float* c, const uint32_t* a, const uint32_t* b) {
    asm volatile("mma.sync.aligned.m16n8k16.row.col.f32.bf16.bf16.f32 "
                 "{%0,%1,%2,%3}, {%4,%5,%6,%7}, {%8,%9}, {%0,%1,%2,%3};"
                 : "+f"(c[0]), "+f"(c[1]), "+f"(c[2]), "+f"(c[3])
                 : "r"(a[0]), "r"(a[1]), "r"(a[2]), "r"(a[3]), "r"(b[0]), "r"(b[1]));
}

template<int BN, int AID, int BID, int CID>
__global__ __launch_bounds__(256)
void mma_nt(const float* __restrict__ Aext, const float* __restrict__ Bext,
            const float* __restrict__ bias, float* __restrict__ Cext,
            int M, int Nc, int K) {
    constexpr int BM = 128, BK = 32;
    constexpr int SP = BK/2 + 4;         // 20 u32 row stride: conflict-free fragment reads
    constexpr int WROWS = 4, WCOLS = 2;
    constexpr int WM = BM / WROWS;       // 32
    constexpr int WN = BN / WCOLS;       // 64 or 32
    constexpr int MT = WM / 16;          // 2
    constexpr int NT = WN / 8;           // 8 or 4
    __shared__ uint32_t As_h[BM][SP];
    __shared__ uint32_t As_l[BM][SP];
    __shared__ uint32_t Bs_h[BN][SP];
    __shared__ uint32_t Bs_l[BN][SP];
    const float* A = (AID < 0) ? Aext : gbuf<AID>();
    const float* B = (BID < 0) ? Bext : gbuf<BID>();
    float*       C = (CID < 0) ? Cext : gbuf<CID>();

    const int tid = threadIdx.x;
    const int wid = tid >> 5, lane = tid & 31;
    const int wr = wid & (WROWS-1), wc = wid / WROWS;
    const int m0 = wr * WM, n0 = wc * WN;
    const int bm = blockIdx.y * BM, bn = blockIdx.x * BN;
    const int lr = lane >> 2, lc = lane & 3;

    float acc[MT][NT][4];
    #pragma unroll
    for (int i = 0; i < MT; i++)
        #pragma unroll
        for (int j = 0; j < NT; j++)
            #pragma unroll
            for (int q = 0; q < 4; q++) acc[i][j][q] = 0.f;

    for (int k0 = 0; k0 < K; k0 += BK) {
        // cooperative load + bf16 hi/lo split (8 float4 per row of 32 floats)
        #pragma unroll
        for (int i = tid; i < BM*8; i += 256) {
            int r = i >> 3, q4 = (i & 7) * 4;           // float offset within row
            int p = q4 >> 1;                             // u32 pair index
            float4 v = *(const float4*)&A[(size_t)(bm+r)*K + k0 + q4];
            As_h[r][p]   = packbf2(v.x, v.y);
            As_h[r][p+1] = packbf2(v.z, v.w);
            As_l[r][p]   = packbf2(v.x - bf_hi_f(v.x), v.y - bf_hi_f(v.y));
            As_l[r][p+1] = packbf2(v.z - bf_hi_f(v.z), v.w - bf_hi_f(v.w));
        }
        #pragma unroll
        for (int i = tid; i < BN*8; i += 256) {
            int r = i >> 3, q4 = (i & 7) * 4;
            int p = q4 >> 1;
            float4 v = *(const float4*)&B[(size_t)(bn+r)*K + k0 + q4];
            Bs_h[r][p]   = packbf2(v.x, v.y);
            Bs_h[r][p+1] = packbf2(v.z, v.w);
            Bs_l[r][p]   = packbf2(v.x - bf_hi_f(v.x), v.y - bf_hi_f(v.y));
            Bs_l[r][p+1] = packbf2(v.z - bf_hi_f(v.z), v.w - bf_hi_f(v.w));
        }
        __syncthreads();
        #pragma unroll
        for (int kc = 0; kc < 2; kc++) {                 // two k16 chunks
            const int pb = kc * 8;                        // pair-index base
            uint32_t ah[MT][4], al[MT][4], bh[NT][2], bl[NT][2];
            #pragma unroll
            for (int i = 0; i < MT; i++) {
                int r = m0 + i*16 + lr;
                ah[i][0] = As_h[r  ][pb + lc];     al[i][0] = As_l[r  ][pb + lc];
                ah[i][1] = As_h[r+8][pb + lc];     al[i][1] = As_l[r+8][pb + lc];
                ah[i][2] = As_h[r  ][pb + lc + 4]; al[i][2] = As_l[r  ][pb + lc + 4];
                ah[i][3] = As_h[r+8][pb + lc + 4]; al[i][3] = As_l[r+8][pb + lc + 4];
            }
            #pragma unroll
            for (int j = 0; j < NT; j++) {
                int r = n0 + j*8 + lr;
                bh[j][0] = Bs_h[r][pb + lc];     bl[j][0] = Bs_l[r][pb + lc];
                bh[j][1] = Bs_h[r][pb + lc + 4]; bl[j][1] = Bs_l[r][pb + lc + 4];
            }
            #pragma unroll
            for (int i = 0; i < MT; i++)
                #pragma unroll
                for (int j = 0; j < NT; j++) {
                    mma16(acc[i][j], al[i], bh[j]);
                    mma16(acc[i][j], ah[i], bl[j]);
                    mma16(acc[i][j], ah[i], bh[j]);
                }
        }
        __syncthreads();
    }
    // epilogue
    #pragma unroll
    for (int i = 0; i < MT; i++) {
        int r = bm + m0 + i*16 + lr;
        #pragma unroll
        for (int j = 0; j < NT; j++) {
            int c = bn + n0 + j*8 + lc*2;
            float b0 = bias ? bias[c]   : 0.f;
            float b1 = bias ? bias[c+1] : 0.f;
            float2 v0 = make_float2(acc[i][j][0] + b0, acc[i][j][1] + b1);
            float2 v1 = make_float2(acc[i][j][2] + b0, acc[i][j][3] + b1);
            *(float2*)&C[(size_t)r*Nc + c]     = v0;
            *(float2*)&C[(size_t)(r+8)*Nc + c] = v1;
        }
    }
}

// ---------------- GCN aggregation: warp per (t,dst) bucket ----------------
template<int XWID, int OUTID>
__global__ void k_gcn_gather(const float* __restrict__ bias) {
    const float* xw = gbuf<XWID>();
    float* out = gbuf<OUTID>();
    int b = (blockIdx.x*blockDim.x + threadIdx.x) >> 5;
    if (b >= TNV) return;
    int lane = threadIdx.x & 31;
    const float4* xw4 = (const float4*)xw;
    float dv = g_dinv[b];
    float sn = dv*dv;
    float4 sv = xw4[(size_t)b*32 + lane];
    float4 acc = make_float4(sn*sv.x, sn*sv.y, sn*sv.z, sn*sv.w);
    int beg = g_offA[b], end = g_offA[b+1];
    for (int k = beg; k < end; k++) {
        int sr = g_srcA[k];
        float nm = g_normA[k];
        float4 v = xw4[(size_t)sr*32 + lane];
        acc.x += nm*v.x; acc.y += nm*v.y; acc.z += nm*v.z; acc.w += nm*v.w;
    }
    float4 bb = ((const float4*)bias)[lane];
    float4 r;
    r.x = fmaxf(acc.x+bb.x, 0.f); r.y = fmaxf(acc.y+bb.y, 0.f);
    r.z = fmaxf(acc.z+bb.z, 0.f); r.w = fmaxf(acc.w+bb.w, 0.f);
    ((float4*)out)[(size_t)b*32 + lane] = r;
}

// ---------------- attention score dots ----------------
__global__ void k_att1(const float* __restrict__ asrc, const float* __restrict__ adst) {
    const float* xw = g_xwg1;
    int w = (blockIdx.x*blockDim.x + threadIdx.x) >> 5;
    if (w >= TNV*4) return;
    int lane = threadIdx.x & 31;
    int i = w >> 2, h = w & 3;
    const float* row = xw + (size_t)i*512 + h*128;
    const float* s = asrc + h*128;
    const float* d = adst + h*128;
    float accs = 0.f, accd = 0.f;
    for (int j = lane; j < 128; j += 32) {
        float v = row[j];
        accs += v*s[j]; accd += v*d[j];
    }
    for (int o = 16; o; o >>= 1) {
        accs += __shfl_down_sync(0xffffffffu, accs, o);
        accd += __shfl_down_sync(0xffffffffu, accd, o);
    }
    if (!lane) { g_as1[w] = accs; g_ad1[w] = accd; }
}

__global__ void k_att2(const float* __restrict__ asrc, const float* __restrict__ adst) {
    const float* xw = g_xwg2;
    int w = (blockIdx.x*blockDim.x + threadIdx.x) >> 5;
    if (w >= TNV) return;
    int lane = threadIdx.x & 31;
    const float* row = xw + (size_t)w*64;
    float accs = row[lane]*asrc[lane] + row[lane+32]*asrc[lane+32];
    float accd = row[lane]*adst[lane] + row[lane+32]*adst[lane+32];
    for (int o = 16; o; o >>= 1) {
        accs += __shfl_down_sync(0xffffffffu, accs, o);
        accd += __shfl_down_sync(0xffffffffu, accd, o);
    }
    if (!lane) { g_as2[w] = accs; g_ad2[w] = accd; }
}

__device__ __forceinline__ float lrelu(float x) { return x > 0.f ? x : 0.2f*x; }

// ---------------- GAT layer-1 aggregation (dst < NN), 512 threads ----------------
__global__ __launch_bounds__(512)
void k_gat1_gather(const float* __restrict__ bias) {
    const float* xw = g_xwg1;
    float* z = g_z1;
    __shared__ float red[512];
    __shared__ float p_sh[128*4];
    __shared__ int   src_sh[128];
    __shared__ float sden[4];
    int d = blockIdx.x;
    int tid = threadIdx.x;
    int h = tid >> 7, c = tid & 127;
    int beg = g_offB[d], end = g_offB[d+1];
    int nE = end - beg;
    float adh = g_ad1[d*4+h];
    float eself = lrelu(g_as1[d*4+h] + adh);
    float lmax = eself;
    for (int k = c; k < nE; k += 128) {
        int s = g_srcB[beg+k];
        lmax = fmaxf(lmax, lrelu(g_as1[s*4+h] + adh));
    }
    red[tid] = lmax; __syncthreads();
    for (int s = 64; s > 0; s >>= 1) {
        if (c < s) red[tid] = fmaxf(red[tid], red[tid+s]);
        __syncthreads();
    }
    float emax = red[h << 7];
    float pself = expf(eself - emax);
    float acc = pself * xw[(size_t)d*512 + tid];
    float ldenom = (c == 0) ? pself : 0.f;
    for (int base = 0; base < nE; base += 128) {
        int kmax = min(128, nE - base);
        __syncthreads();
        if (tid < kmax) src_sh[tid] = g_srcB[beg + base + tid];
        __syncthreads();
        if (c < kmax) {
            int s = src_sh[c];
            p_sh[c*4 + h] = expf(lrelu(g_as1[s*4+h] + adh) - emax);
        }
        __syncthreads();
        for (int kk = 0; kk < kmax; kk++) {
            float p = p_sh[kk*4 + h];
            acc += p * xw[(size_t)src_sh[kk]*512 + tid];
            if (c == 0) ldenom += p;
        }
    }
    if (c == 0) sden[h] = ldenom;
    __syncthreads();
    float o = acc / (sden[h] + 1e-16f) + bias[tid];
    z[(size_t)d*512 + tid] = fmaxf(o, 0.f);
}

// ---------------- GAT layer-2 aggregation (dst < NN), 64 threads ----------------
__global__ __launch_bounds__(64)
void k_gat2_gather(const float* __restrict__ bias) {
    const float* xw = g_xwg2;
    float* z = g_z2;
    __shared__ float red[64];
    __shared__ float p_sh[64];
    __shared__ int   src_sh[64];
    __shared__ float sden;
    int d = blockIdx.x;
    int tid = threadIdx.x;
    int beg = g_offB[d], end = g_offB[d+1];
    int nE = end - beg;
    float adh = g_ad2[d];
    float eself = lrelu(g_as2[d] + adh);
    float lmax = eself;
    for (int k = tid; k < nE; k += 64)
        lmax = fmaxf(lmax, lrelu(g_as2[g_srcB[beg+k]] + adh));
    red[tid] = lmax; __syncthreads();
    for (int s = 32; s > 0; s >>= 1) {
        if (tid < s) red[tid] = fmaxf(red[tid], red[tid+s]);
        __syncthreads();
    }
    float emax = red[0];
    float pself = expf(eself - emax);
    float acc = pself * xw[d*64 + tid];
    float ldenom = (tid == 0) ? pself : 0.f;
    for (int base = 0; base < nE; base += 64) {
        int kmax = min(64, nE - base);
        __syncthreads();
        if (tid < kmax) {
            int s = g_srcB[beg + base + tid];
            src_sh[tid] = s;
            p_sh[tid] = expf(lrelu(g_as2[s] + adh) - emax);
        }
        __syncthreads();
        for (int kk = 0; kk < kmax; kk++) {
            float p = p_sh[kk];
            acc += p * xw[src_sh[kk]*64 + tid];
            if (tid == 0) ldenom += p;
        }
    }
    if (tid == 0) sden = ldenom;
    __syncthreads();
    z[d*64 + tid] = acc / (sden + 1e-16f) + bias[tid];
}

// ---------------- self-loop-only nodes (row >= NN) ----------------
__global__ void k_zrest1(const float* __restrict__ bias) {
    int i = blockIdx.x*blockDim.x + threadIdx.x;
    if (i >= (TNV-NN)*512) return;
    size_t off = (size_t)NN*512 + i;
    g_z1[off] = fmaxf(g_xwg1[off] + bias[i & 511], 0.f);
}
__global__ void k_zrest2(const float* __restrict__ bias) {
    int i = blockIdx.x*blockDim.x + threadIdx.x;
    if (i >= (TNV-NN)*64) return;
    int off = NN*64 + i;
    g_z2[off] = g_xwg2[off] + bias[i & 63];
}

// ---------------- link prediction (edge_label_index is INT32) ----------------
__global__ void k_link(const int* __restrict__ eli, float* __restrict__ out) {
    const float* z = g_z2;
    int w = (blockIdx.x*blockDim.x + threadIdx.x) >> 5;
    if (w >= ELN) return;
    int lane = threadIdx.x & 31;
    int u = eli[w] & (TNV-1);
    int v = eli[ELN + w] & (TNV-1);
    float s = z[u*64+lane]*z[v*64+lane] + z[u*64+lane+32]*z[v*64+lane+32];
    for (int o = 16; o; o >>= 1) s += __shfl_down_sync(0xffffffffu, s, o);
    if (!lane) out[w] = s;
}

// ---------------- launch ----------------
extern "C" void kernel_launch(void* const* d_in, const int* in_sizes, int n_in,
                              void* d_out, int out_size) {
    const float* x    = (const float*)d_in[0];
    const int*   ei   = (const int*)d_in[1];
    const float* ea   = (const float*)d_in[2];
    const int*   eli  = (const int*)d_in[3];
    const float* c1w = (const float*)d_in[4];
    const float* c1b = (const float*)d_in[5];
    const float* c2w = (const float*)d_in[6];
    const float* c2b = (const float*)d_in[7];
    const float* g1w = (const float*)d_in[8];
    const float* g1as = (const float*)d_in[9];
    const float* g1ad = (const float*)d_in[10];
    const float* g1b = (const float*)d_in[11];
    const float* g2w = (const float*)d_in[12];
    const float* g2as = (const float*)d_in[13];
    const float* g2ad = (const float*)d_in[14];
    const float* g2b = (const float*)d_in[15];
    const float* fcw = (const float*)d_in[16];
    const float* fcb = (const float*)d_in[17];

    float* out  = (float*)d_out;
    float* link = out;
    float* hop  = out + ELN;

    // GAT1 GEMM kept at stream-launch index 3 (ncu -s 5 -c 1 samples it).
    k_init<<<TNV/256, 256>>>();                                   // 0
    k_hist<<<TEV/256, 256>>>(ei, ea);                             // 1
    k_scanA<<<1, 1024>>>();                                       // 2
    mma_nt<128, BUF_EXT,BUF_EXT,BUF_XWG1><<<dim3(512/128,TNV/128), 256>>>(x, g1w, nullptr, nullptr, TNV, 512, 64);  // 3
    k_scanB<<<1, 1024>>>();                                       // 4
    k_dinv<<<TNV/256, 256>>>();                                   // 5
    k_fill<<<TEV/256, 256>>>(ei, ea);                             // 6
    k_weff<<<(NN*HID)/256, 256>>>(fcw);                           // 7

    // --- GCN hop branch ---
    mma_nt<128, BUF_EXT,BUF_EXT,BUF_XW1><<<dim3(1,TNV/128), 256>>>(x, c1w, nullptr, nullptr, TNV, 128, 64);
    k_gcn_gather<BUF_XW1,BUF_H1><<<TNV/4, 128>>>(c1b);
    mma_nt<128, BUF_H1,BUF_EXT,BUF_XW2><<<dim3(1,TNV/128), 256>>>(nullptr, c2w, nullptr, nullptr, TNV, 128, 128);
    k_gcn_gather<BUF_XW2,BUF_H2><<<TNV/4, 128>>>(c2b);
    mma_nt<128, BUF_H2,BUF_WEFF,BUF_EXT><<<dim3(NN/128,TNV/128), 256>>>(nullptr, nullptr, fcb, hop, TNV, NN, 128);

    // --- GAT link branch (xwg1 GEMM already issued above) ---
    k_att1<<<TNV, 128>>>(g1as, g1ad);
    k_gat1_gather<<<NN, 512>>>(g1b);
    k_zrest1<<<((TNV-NN)*512)/256, 256>>>(g1b);
    mma_nt<64, BUF_Z1,BUF_EXT,BUF_XWG2><<<dim3(1,TNV/128), 256>>>(nullptr, g2w, nullptr, nullptr, TNV, 64, 512);
    k_att2<<<TNV/4, 128>>>(g2as, g2ad);
    k_gat2_gather<<<NN, 64>>>(g2b);
    k_zrest2<<<((TNV-NN)*64)/256, 256>>>(g2b);
    k_link<<<ELN/4, 128>>>(eli, link);
}

// round 7
// speedup vs baseline: 2.5354x; 1.0617x over previous
#include <cuda_runtime.h>
#include <cuda_bf16.h>
#include <math.h>
#include <stdint.h>

#define TT   16
#define NN   2048
#define EE   16384
#define ELN  8192
#define TNV  (TT*NN)   /* 32768 */
#define TEV  (TT*EE)   /* 262144 */
#define HID  128
#define DIN  64

// ---------------- scratch (static device allocations only) ----------------
__device__ float g_deg[TNV];
__device__ float g_dinv[TNV];
__device__ int   g_cntA[TNV];
__device__ int   g_offA[TNV+1];
__device__ int   g_curA[TNV];
__device__ int   g_cntB[NN];
__device__ int   g_offB[NN+1];
__device__ int   g_curB[NN];
__device__ int   g_srcA[TEV];
__device__ float g_normA[TEV];
__device__ int   g_srcB[TEV];

__device__ __align__(16) float g_xw1[TNV*HID];
__device__ __align__(16) float g_h1 [TNV*HID];
__device__ __align__(16) float g_xw2[TNV*HID];
__device__ __align__(16) float g_h2 [TNV*HID];
__device__ __align__(16) float g_weff[NN*HID];

__device__ __align__(16) float g_xwg1[(size_t)TNV*512];
__device__ float g_as1[TNV*4];
__device__ float g_ad1[TNV*4];
__device__ __align__(16) float g_z1 [(size_t)TNV*512];
__device__ __align__(16) float g_xwg2[TNV*64];
__device__ float g_as2[TNV];
__device__ float g_ad2[TNV];
__device__ __align__(16) float g_z2 [TNV*64];

#define BUF_EXT   (-1)
#define BUF_XW1   0
#define BUF_H1    1
#define BUF_XW2   2
#define BUF_H2    3
#define BUF_WEFF  4
#define BUF_XWG1  5
#define BUF_Z1    6
#define BUF_XWG2  7
#define BUF_Z2    8

template<int ID>
__device__ __forceinline__ float* gbuf() {
    if (ID == BUF_XW1)  return g_xw1;
    if (ID == BUF_H1)   return g_h1;
    if (ID == BUF_XW2)  return g_xw2;
    if (ID == BUF_H2)   return g_h2;
    if (ID == BUF_WEFF) return g_weff;
    if (ID == BUF_XWG1) return g_xwg1;
    if (ID == BUF_Z1)   return g_z1;
    if (ID == BUF_XWG2) return g_xwg2;
    if (ID == BUF_Z2)   return g_z2;
    return nullptr;
}

// ---------------- init ----------------
__global__ void k_init() {
    int i = blockIdx.x*blockDim.x + threadIdx.x;
    if (i < TNV) { g_deg[i]=0.f; g_cntA[i]=0; g_curA[i]=0; }
    if (i < NN)  { g_cntB[i]=0; g_curB[i]=0; }
}

// ---------------- degree + CSR histograms (edge_index is INT32) ----------------
__global__ void k_hist(const int* __restrict__ ei, const float* __restrict__ ea) {
    int idx = blockIdx.x*blockDim.x + threadIdx.x;
    if (idx >= TEV) return;
    int t = idx >> 14, e = idx & (EE-1);
    int dst = ei[(t*2+1)*EE + e] & (NN-1);
    float w = ea[idx];
    atomicAdd(&g_deg[t*NN+dst], w);
    atomicAdd(&g_cntA[t*NN+dst], 1);
    atomicAdd(&g_cntB[dst], 1);
}

// single-block exclusive scan (n multiple of 1024)
__device__ void scan_impl(const int* cnt, int* off, int n) {
    __shared__ int part[1024];
    int tid = threadIdx.x;
    int per = n / 1024;
    int base = tid * per;
    int s = 0;
    for (int i = 0; i < per; i++) s += cnt[base+i];
    part[tid] = s; __syncthreads();
    for (int d = 1; d < 1024; d <<= 1) {
        int v = (tid >= d) ? part[tid-d] : 0;
        __syncthreads();
        part[tid] += v;
        __syncthreads();
    }
    int run = (tid == 0) ? 0 : part[tid-1];
    for (int i = 0; i < per; i++) { off[base+i] = run; run += cnt[base+i]; }
    if (tid == 1023) off[n] = run;
}
__global__ void k_scanA() { scan_impl(g_cntA, g_offA, TNV); }
__global__ void k_scanB() { scan_impl(g_cntB, g_offB, NN); }

__global__ void k_dinv() {
    int i = blockIdx.x*blockDim.x + threadIdx.x;
    if (i < TNV) g_dinv[i] = 1.0f / sqrtf(g_deg[i] + 1.0f);
}

__global__ void k_fill(const int* __restrict__ ei, const float* __restrict__ ea) {
    int idx = blockIdx.x*blockDim.x + threadIdx.x;
    if (idx >= TEV) return;
    int t = idx >> 14, e = idx & (EE-1);
    int src = ei[(t*2  )*EE + e] & (NN-1);
    int dst = ei[(t*2+1)*EE + e] & (NN-1);
    float w = ea[idx];
    float nm = g_dinv[t*NN+src] * w * g_dinv[t*NN+dst];
    int bA = t*NN + dst;
    int p = atomicAdd(&g_curA[bA], 1);
    int slot = g_offA[bA] + p;
    g_srcA[slot] = t*NN + src;
    g_normA[slot] = nm;
    int q = atomicAdd(&g_curB[dst], 1);
    g_srcB[g_offB[dst] + q] = src;
}

__global__ void k_weff(const float* __restrict__ fcw) {
    int i = blockIdx.x*blockDim.x + threadIdx.x;
    if (i >= NN*HID) return;
    int r = i >> 7, c = i & 127;
    g_weff[i] = fcw[r*256 + c] + fcw[r*256 + 128 + c];
}

// ============ bf16x3 MMA GEMM: C[M,Nc] = A[M,K]*B[Nc,K]^T (+bias) ============
// fp32 split into bf16 hi+lo at load time; mainloop = LDS + m16n8k16 bf16 MMA.
// D ~= Ah*Bh + Ah*Bl + Al*Bh  (lo*lo term ~2^-16 relative, dropped)
// Register-lean mainloop (B-frags loaded per column) so 2 CTAs fit per SM.
__device__ __forceinline__ uint32_t packbf2(float lo_elem, float hi_elem) {
    uint32_t a = (uint32_t)__bfloat16_as_ushort(__float2bfloat16_rn(lo_elem));
    uint32_t b = (uint32_t)__bfloat16_as_ushort(__float2bfloat16_rn(hi_elem));
    return (b << 16) | a;
}
__device__ __forceinline__ float bf_hi_f(float x) {
    return __bfloat162float(__float2bfloat16_rn(x));
}
__device__ __forceinline__ void mma16(float* c, const uint32_t* a, uint32_t b0, uint32_t b1) {
    asm volatile("mma.sync.aligned.m16n8k16.row.col.f32.bf16.bf16.f32 "
                 "{%0,%1,%2,%3}, {%4,%5,%6,%7}, {%8,%9}, {%0,%1,%2,%3};"
                 : "+f"(c[0]), "+f"(c[1]), "+f"(c[2]), "+f"(c[3])
                 : "r"(a[0]), "r"(a[1]), "r"(a[2]), "r"(a[3]), "r"(b0), "r"(b1));
}

template<int BN, int AID, int BID, int CID>
__global__ __launch_bounds__(256, 2)
void mma_nt(const float* __restrict__ Aext, const float* __restrict__ Bext,
            const float* __restrict__ bias, float* __restrict__ Cext,
            int M, int Nc, int K) {
    constexpr int BM = 128, BK = 32;
    constexpr int SP = BK/2 + 4;         // 20 u32 row stride: conflict-free fragment reads
    constexpr int WROWS = 4, WCOLS = 2;
    constexpr int WM = BM / WROWS;       // 32
    constexpr int WN = BN / WCOLS;       // 64 or 32
    constexpr int MT = WM / 16;          // 2
    constexpr int NT = WN / 8;           // 8 or 4
    __shared__ uint32_t As_h[BM][SP];
    __shared__ uint32_t As_l[BM][SP];
    __shared__ uint32_t Bs_h[BN][SP];
    __shared__ uint32_t Bs_l[BN][SP];
    const float* A = (AID < 0) ? Aext : gbuf<AID>();
    const float* B = (BID < 0) ? Bext : gbuf<BID>();
    float*       C = (CID < 0) ? Cext : gbuf<CID>();

    const int tid = threadIdx.x;
    const int wid = tid >> 5, lane = tid & 31;
    const int wr = wid & (WROWS-1), wc = wid / WROWS;
    const int m0 = wr * WM, n0 = wc * WN;
    const int bm = blockIdx.y * BM, bn = blockIdx.x * BN;
    const int lr = lane >> 2, lc = lane & 3;

    float acc[MT][NT][4];
    #pragma unroll
    for (int i = 0; i < MT; i++)
        #pragma unroll
        for (int j = 0; j < NT; j++)
            #pragma unroll
            for (int q = 0; q < 4; q++) acc[i][j][q] = 0.f;

    for (int k0 = 0; k0 < K; k0 += BK) {
        // cooperative load + bf16 hi/lo split (8 float4 per row of 32 floats)
        #pragma unroll
        for (int i = tid; i < BM*8; i += 256) {
            int r = i >> 3, q4 = (i & 7) * 4;
            int p = q4 >> 1;
            float4 v = *(const float4*)&A[(size_t)(bm+r)*K + k0 + q4];
            As_h[r][p]   = packbf2(v.x, v.y);
            As_h[r][p+1] = packbf2(v.z, v.w);
            As_l[r][p]   = packbf2(v.x - bf_hi_f(v.x), v.y - bf_hi_f(v.y));
            As_l[r][p+1] = packbf2(v.z - bf_hi_f(v.z), v.w - bf_hi_f(v.w));
        }
        #pragma unroll
        for (int i = tid; i < BN*8; i += 256) {
            int r = i >> 3, q4 = (i & 7) * 4;
            int p = q4 >> 1;
            float4 v = *(const float4*)&B[(size_t)(bn+r)*K + k0 + q4];
            Bs_h[r][p]   = packbf2(v.x, v.y);
            Bs_h[r][p+1] = packbf2(v.z, v.w);
            Bs_l[r][p]   = packbf2(v.x - bf_hi_f(v.x), v.y - bf_hi_f(v.y));
            Bs_l[r][p+1] = packbf2(v.z - bf_hi_f(v.z), v.w - bf_hi_f(v.w));
        }
        __syncthreads();
        #pragma unroll
        for (int kc = 0; kc < 2; kc++) {                 // two k16 chunks
            const int pb = kc * 8;
            uint32_t ah[MT][4], al[MT][4];
            #pragma unroll
            for (int i = 0; i < MT; i++) {
                int r = m0 + i*16 + lr;
                ah[i][0] = As_h[r  ][pb + lc];     al[i][0] = As_l[r  ][pb + lc];
                ah[i][1] = As_h[r+8][pb + lc];     al[i][1] = As_l[r+8][pb + lc];
                ah[i][2] = As_h[r  ][pb + lc + 4]; al[i][2] = As_l[r  ][pb + lc + 4];
                ah[i][3] = As_h[r+8][pb + lc + 4]; al[i][3] = As_l[r+8][pb + lc + 4];
            }
            #pragma unroll
            for (int j = 0; j < NT; j++) {               // B-frags loaded per column: low reg pressure
                int r = n0 + j*8 + lr;
                uint32_t bh0 = Bs_h[r][pb + lc];
                uint32_t bh1 = Bs_h[r][pb + lc + 4];
                uint32_t bl0 = Bs_l[r][pb + lc];
                uint32_t bl1 = Bs_l[r][pb + lc + 4];
                #pragma unroll
                for (int i = 0; i < MT; i++) {
                    mma16(acc[i][j], al[i], bh0, bh1);
                    mma16(acc[i][j], ah[i], bl0, bl1);
                    mma16(acc[i][j], ah[i], bh0, bh1);
                }
            }
        }
        __syncthreads();
    }
    // epilogue
    #pragma unroll
    for (int i = 0; i < MT; i++) {
        int r = bm + m0 + i*16 + lr;
        #pragma unroll
        for (int j = 0; j < NT; j++) {
            int c = bn + n0 + j*8 + lc*2;
            float b0 = bias ? bias[c]   : 0.f;
            float b1 = bias ? bias[c+1] : 0.f;
            float2 v0 = make_float2(acc[i][j][0] + b0, acc[i][j][1] + b1);
            float2 v1 = make_float2(acc[i][j][2] + b0, acc[i][j][3] + b1);
            *(float2*)&C[(size_t)r*Nc + c]     = v0;
            *(float2*)&C[(size_t)(r+8)*Nc + c] = v1;
        }
    }
}

// ---------------- GCN aggregation: warp per (t,dst) bucket ----------------
template<int XWID, int OUTID>
__global__ void k_gcn_gather(const float* __restrict__ bias) {
    const float* xw = gbuf<XWID>();
    float* out = gbuf<OUTID>();
    int b = (blockIdx.x*blockDim.x + threadIdx.x) >> 5;
    if (b >= TNV) return;
    int lane = threadIdx.x & 31;
    const float4* xw4 = (const float4*)xw;
    float dv = g_dinv[b];
    float sn = dv*dv;
    float4 sv = xw4[(size_t)b*32 + lane];
    float4 acc = make_float4(sn*sv.x, sn*sv.y, sn*sv.z, sn*sv.w);
    int beg = g_offA[b], end = g_offA[b+1];
    for (int k = beg; k < end; k++) {
        int sr = g_srcA[k];
        float nm = g_normA[k];
        float4 v = xw4[(size_t)sr*32 + lane];
        acc.x += nm*v.x; acc.y += nm*v.y; acc.z += nm*v.z; acc.w += nm*v.w;
    }
    float4 bb = ((const float4*)bias)[lane];
    float4 r;
    r.x = fmaxf(acc.x+bb.x, 0.f); r.y = fmaxf(acc.y+bb.y, 0.f);
    r.z = fmaxf(acc.z+bb.z, 0.f); r.w = fmaxf(acc.w+bb.w, 0.f);
    ((float4*)out)[(size_t)b*32 + lane] = r;
}

// ---------------- attention score dots ----------------
__global__ void k_att1(const float* __restrict__ asrc, const float* __restrict__ adst) {
    const float* xw = g_xwg1;
    int w = (blockIdx.x*blockDim.x + threadIdx.x) >> 5;
    if (w >= TNV*4) return;
    int lane = threadIdx.x & 31;
    int i = w >> 2, h = w & 3;
    const float* row = xw + (size_t)i*512 + h*128;
    const float* s = asrc + h*128;
    const float* d = adst + h*128;
    float accs = 0.f, accd = 0.f;
    for (int j = lane; j < 128; j += 32) {
        float v = row[j];
        accs += v*s[j]; accd += v*d[j];
    }
    for (int o = 16; o; o >>= 1) {
        accs += __shfl_down_sync(0xffffffffu, accs, o);
        accd += __shfl_down_sync(0xffffffffu, accd, o);
    }
    if (!lane) { g_as1[w] = accs; g_ad1[w] = accd; }
}

__global__ void k_att2(const float* __restrict__ asrc, const float* __restrict__ adst) {
    const float* xw = g_xwg2;
    int w = (blockIdx.x*blockDim.x + threadIdx.x) >> 5;
    if (w >= TNV) return;
    int lane = threadIdx.x & 31;
    const float* row = xw + (size_t)w*64;
    float accs = row[lane]*asrc[lane] + row[lane+32]*asrc[lane+32];
    float accd = row[lane]*adst[lane] + row[lane+32]*adst[lane+32];
    for (int o = 16; o; o >>= 1) {
        accs += __shfl_down_sync(0xffffffffu, accs, o);
        accd += __shfl_down_sync(0xffffffffu, accd, o);
    }
    if (!lane) { g_as2[w] = accs; g_ad2[w] = accd; }
}

__device__ __forceinline__ float lrelu(float x) { return x > 0.f ? x : 0.2f*x; }

// ---------------- GAT layer-1 aggregation (dst < NN), 512 threads ----------------
__global__ __launch_bounds__(512)
void k_gat1_gather(const float* __restrict__ bias) {
    const float* xw = g_xwg1;
    float* z = g_z1;
    __shared__ float red[512];
    __shared__ float p_sh[128*4];
    __shared__ int   src_sh[128];
    __shared__ float sden[4];
    int d = blockIdx.x;
    int tid = threadIdx.x;
    int h = tid >> 7, c = tid & 127;
    int beg = g_offB[d], end = g_offB[d+1];
    int nE = end - beg;
    float adh = g_ad1[d*4+h];
    float eself = lrelu(g_as1[d*4+h] + adh);
    float lmax = eself;
    for (int k = c; k < nE; k += 128) {
        int s = g_srcB[beg+k];
        lmax = fmaxf(lmax, lrelu(g_as1[s*4+h] + adh));
    }
    red[tid] = lmax; __syncthreads();
    for (int s = 64; s > 0; s >>= 1) {
        if (c < s) red[tid] = fmaxf(red[tid], red[tid+s]);
        __syncthreads();
    }
    float emax = red[h << 7];
    float pself = expf(eself - emax);
    float acc = pself * xw[(size_t)d*512 + tid];
    float ldenom = (c == 0) ? pself : 0.f;
    for (int base = 0; base < nE; base += 128) {
        int kmax = min(128, nE - base);
        __syncthreads();
        if (tid < kmax) src_sh[tid] = g_srcB[beg + base + tid];
        __syncthreads();
        if (c < kmax) {
            int s = src_sh[c];
            p_sh[c*4 + h] = expf(lrelu(g_as1[s*4+h] + adh) - emax);
        }
        __syncthreads();
        for (int kk = 0; kk < kmax; kk++) {
            float p = p_sh[kk*4 + h];
            acc += p * xw[(size_t)src_sh[kk]*512 + tid];
            if (c == 0) ldenom += p;
        }
    }
    if (c == 0) sden[h] = ldenom;
    __syncthreads();
    float o = acc / (sden[h] + 1e-16f) + bias[tid];
    z[(size_t)d*512 + tid] = fmaxf(o, 0.f);
}

// ---------------- GAT layer-2 aggregation (dst < NN), 64 threads ----------------
__global__ __launch_bounds__(64)
void k_gat2_gather(const float* __restrict__ bias) {
    const float* xw = g_xwg2;
    float* z = g_z2;
    __shared__ float red[64];
    __shared__ float p_sh[64];
    __shared__ int   src_sh[64];
    __shared__ float sden;
    int d = blockIdx.x;
    int tid = threadIdx.x;
    int beg = g_offB[d], end = g_offB[d+1];
    int nE = end - beg;
    float adh = g_ad2[d];
    float eself = lrelu(g_as2[d] + adh);
    float lmax = eself;
    for (int k = tid; k < nE; k += 64)
        lmax = fmaxf(lmax, lrelu(g_as2[g_srcB[beg+k]] + adh));
    red[tid] = lmax; __syncthreads();
    for (int s = 32; s > 0; s >>= 1) {
        if (tid < s) red[tid] = fmaxf(red[tid], red[tid+s]);
        __syncthreads();
    }
    float emax = red[0];
    float pself = expf(eself - emax);
    float acc = pself * xw[d*64 + tid];
    float ldenom = (tid == 0) ? pself : 0.f;
    for (int base = 0; base < nE; base += 64) {
        int kmax = min(64, nE - base);
        __syncthreads();
        if (tid < kmax) {
            int s = g_srcB[beg + base + tid];
            src_sh[tid] = s;
            p_sh[tid] = expf(lrelu(g_as2[s] + adh) - emax);
        }
        __syncthreads();
        for (int kk = 0; kk < kmax; kk++) {
            float p = p_sh[kk];
            acc += p * xw[src_sh[kk]*64 + tid];
            if (tid == 0) ldenom += p;
        }
    }
    if (tid == 0) sden = ldenom;
    __syncthreads();
    z[d*64 + tid] = acc / (sden + 1e-16f) + bias[tid];
}

// ---------------- self-loop-only nodes (row >= NN) ----------------
__global__ void k_zrest1(const float* __restrict__ bias) {
    int i = blockIdx.x*blockDim.x + threadIdx.x;
    if (i >= (TNV-NN)*512) return;
    size_t off = (size_t)NN*512 + i;
    g_z1[off] = fmaxf(g_xwg1[off] + bias[i & 511], 0.f);
}
__global__ void k_zrest2(const float* __restrict__ bias) {
    int i = blockIdx.x*blockDim.x + threadIdx.x;
    if (i >= (TNV-NN)*64) return;
    int off = NN*64 + i;
    g_z2[off] = g_xwg2[off] + bias[i & 63];
}

// ---------------- link prediction (edge_label_index is INT32) ----------------
__global__ void k_link(const int* __restrict__ eli, float* __restrict__ out) {
    const float* z = g_z2;
    int w = (blockIdx.x*blockDim.x + threadIdx.x) >> 5;
    if (w >= ELN) return;
    int lane = threadIdx.x & 31;
    int u = eli[w] & (TNV-1);
    int v = eli[ELN + w] & (TNV-1);
    float s = z[u*64+lane]*z[v*64+lane] + z[u*64+lane+32]*z[v*64+lane+32];
    for (int o = 16; o; o >>= 1) s += __shfl_down_sync(0xffffffffu, s, o);
    if (!lane) out[w] = s;
}

// ---------------- launch ----------------
extern "C" void kernel_launch(void* const* d_in, const int* in_sizes, int n_in,
                              void* d_out, int out_size) {
    const float* x    = (const float*)d_in[0];
    const int*   ei   = (const int*)d_in[1];
    const float* ea   = (const float*)d_in[2];
    const int*   eli  = (const int*)d_in[3];
    const float* c1w = (const float*)d_in[4];
    const float* c1b = (const float*)d_in[5];
    const float* c2w = (const float*)d_in[6];
    const float* c2b = (const float*)d_in[7];
    const float* g1w = (const float*)d_in[8];
    const float* g1as = (const float*)d_in[9];
    const float* g1ad = (const float*)d_in[10];
    const float* g1b = (const float*)d_in[11];
    const float* g2w = (const float*)d_in[12];
    const float* g2as = (const float*)d_in[13];
    const float* g2ad = (const float*)d_in[14];
    const float* g2b = (const float*)d_in[15];
    const float* fcw = (const float*)d_in[16];
    const float* fcb = (const float*)d_in[17];

    float* out  = (float*)d_out;
    float* link = out;
    float* hop  = out + ELN;

    // GAT1 GEMM kept at stream-launch index 3 (ncu -s 5 -c 1 samples it).
    k_init<<<TNV/256, 256>>>();                                   // 0
    k_hist<<<TEV/256, 256>>>(ei, ea);                             // 1
    k_scanA<<<1, 1024>>>();                                       // 2
    mma_nt<128, BUF_EXT,BUF_EXT,BUF_XWG1><<<dim3(512/128,TNV/128), 256>>>(x, g1w, nullptr, nullptr, TNV, 512, 64);  // 3
    k_scanB<<<1, 1024>>>();                                       // 4
    k_dinv<<<TNV/256, 256>>>();                                   // 5
    k_fill<<<TEV/256, 256>>>(ei, ea);                             // 6
    k_weff<<<(NN*HID)/256, 256>>>(fcw);                           // 7

    // --- GCN hop branch ---
    mma_nt<128, BUF_EXT,BUF_EXT,BUF_XW1><<<dim3(1,TNV/128), 256>>>(x, c1w, nullptr, nullptr, TNV, 128, 64);
    k_gcn_gather<BUF_XW1,BUF_H1><<<TNV/4, 128>>>(c1b);
    mma_nt<128, BUF_H1,BUF_EXT,BUF_XW2><<<dim3(1,TNV/128), 256>>>(nullptr, c2w, nullptr, nullptr, TNV, 128, 128);
    k_gcn_gather<BUF_XW2,BUF_H2><<<TNV/4, 128>>>(c2b);
    mma_nt<128, BUF_H2,BUF_WEFF,BUF_EXT><<<dim3(NN/128,TNV/128), 256>>>(nullptr, nullptr, fcb, hop, TNV, NN, 128);

    // --- GAT link branch (xwg1 GEMM already issued above) ---
    k_att1<<<TNV, 128>>>(g1as, g1ad);
    k_gat1_gather<<<NN, 512>>>(g1b);
    k_zrest1<<<((TNV-NN)*512)/256, 256>>>(g1b);
    mma_nt<64, BUF_Z1,BUF_EXT,BUF_XWG2><<<dim3(1,TNV/128), 256>>>(nullptr, g2w, nullptr, nullptr, TNV, 64, 512);
    k_att2<<<TNV/4, 128>>>(g2as, g2ad);
    k_gat2_gather<<<NN, 64>>>(g2b);
    k_zrest2<<<((TNV-NN)*64)/256, 256>>>(g2b);
    k_link<<<ELN/4, 128>>>(eli, link);
}